// round 1
// baseline (speedup 1.0000x reference)
#include <cuda_runtime.h>
#include <math.h>

#define SEQ   4096
#define DIM   1024
#define NHEAD 16
#define DHEAD 64
#define PADF  68   // padded smem row (floats) for flash tiles, keeps float4 alignment

// Scratch (no cudaMalloc allowed): 5 x 16 MB fp32 buffers
__device__ float g_h [SEQ*DIM];
__device__ float g_q [SEQ*DIM];
__device__ float g_k [SEQ*DIM];
__device__ float g_v [SEQ*DIM];
__device__ float g_ao[SEQ*DIM];

// ---------------------------------------------------------------------------
// h = x + positional_encoding
// ---------------------------------------------------------------------------
__global__ __launch_bounds__(256) void add_pe_kernel(const float* __restrict__ x,
                                                     float* __restrict__ h) {
    int row = blockIdx.x;
    int c0  = threadIdx.x * 4;
    const float kf = -9.210340371976184f / (float)DIM;   // -ln(10000)/D
    float4 xv = *reinterpret_cast<const float4*>(x + (size_t)row * DIM + c0);
    float v[4] = {xv.x, xv.y, xv.z, xv.w};
    float o[4];
#pragma unroll
    for (int e = 0; e < 4; e++) {
        int c = c0 + e;
        float div = expf((float)(c & ~1) * kf);
        float arg = (float)row * div;
        o[e] = v[e] + ((c & 1) ? cosf(arg) : sinf(arg));
    }
    *reinterpret_cast<float4*>(h + (size_t)row * DIM + c0) =
        make_float4(o[0], o[1], o[2], o[3]);
}

// ---------------------------------------------------------------------------
// C[M,N] = A[M,K] @ B[K,N] + bias[N]   (classic 128x128x8 fp32 SGEMM)
// M,N,K multiples of 128 / 8; 256 threads; 8x8 per-thread microtile
// ---------------------------------------------------------------------------
__global__ __launch_bounds__(256) void sgemm_bias(const float* __restrict__ A,
                                                  const float* __restrict__ B,
                                                  const float* __restrict__ bias,
                                                  float* __restrict__ C,
                                                  int M, int N, int K) {
    const int BM = 128, BN = 128, BK = 8, TM = 8, TN = 8;
    __shared__ float As[BK][BM];
    __shared__ float Bs[BK][BN];

    int tid  = threadIdx.x;
    int trow = tid >> 4;          // 0..15
    int tcol = tid & 15;          // 0..15

    const float* Ab = A + (size_t)blockIdx.y * BM * K;
    const float* Bb = B + (size_t)blockIdx.x * BN;

    int aRow = tid >> 1;          // 0..127
    int aCol = (tid & 1) * 4;     // 0 or 4
    int bRow = tid >> 5;          // 0..7
    int bCol = (tid & 31) * 4;    // 0..124

    float acc[TM][TN] = {};

    for (int k0 = 0; k0 < K; k0 += BK) {
        float4 av = *reinterpret_cast<const float4*>(Ab + (size_t)aRow * K + k0 + aCol);
        As[aCol + 0][aRow] = av.x;
        As[aCol + 1][aRow] = av.y;
        As[aCol + 2][aRow] = av.z;
        As[aCol + 3][aRow] = av.w;
        float4 bvv = *reinterpret_cast<const float4*>(Bb + (size_t)(k0 + bRow) * N + bCol);
        *reinterpret_cast<float4*>(&Bs[bRow][bCol]) = bvv;
        __syncthreads();
#pragma unroll
        for (int k = 0; k < BK; k++) {
            float rm[TM], rn[TN];
            const float4* ap = reinterpret_cast<const float4*>(&As[k][trow * TM]);
            float4 a0 = ap[0], a1 = ap[1];
            rm[0]=a0.x; rm[1]=a0.y; rm[2]=a0.z; rm[3]=a0.w;
            rm[4]=a1.x; rm[5]=a1.y; rm[6]=a1.z; rm[7]=a1.w;
            const float4* bp = reinterpret_cast<const float4*>(&Bs[k][tcol * TN]);
            float4 b0 = bp[0], b1 = bp[1];
            rn[0]=b0.x; rn[1]=b0.y; rn[2]=b0.z; rn[3]=b0.w;
            rn[4]=b1.x; rn[5]=b1.y; rn[6]=b1.z; rn[7]=b1.w;
#pragma unroll
            for (int i = 0; i < TM; i++)
#pragma unroll
                for (int j = 0; j < TN; j++)
                    acc[i][j] = fmaf(rm[i], rn[j], acc[i][j]);
        }
        __syncthreads();
    }

#pragma unroll
    for (int i = 0; i < TM; i++) {
        int r = blockIdx.y * BM + trow * TM + i;
#pragma unroll
        for (int j = 0; j < TN; j += 4) {
            int c = blockIdx.x * BN + tcol * TN + j;
            float4 o;
            o.x = acc[i][j + 0] + bias[c + 0];
            o.y = acc[i][j + 1] + bias[c + 1];
            o.z = acc[i][j + 2] + bias[c + 2];
            o.w = acc[i][j + 3] + bias[c + 3];
            *reinterpret_cast<float4*>(C + (size_t)r * N + c) = o;
        }
    }
}

// ---------------------------------------------------------------------------
// Flash attention, fp32, per-(head, 64-row q-tile) block.
// Smem tiles stored so the kk-loop reads are contiguous float4s.
// ---------------------------------------------------------------------------
__global__ __launch_bounds__(256) void flash_kernel(const float* __restrict__ Q,
                                                    const float* __restrict__ K,
                                                    const float* __restrict__ V,
                                                    float* __restrict__ O) {
    extern __shared__ float sm[];
    float* Qt = sm;               // [kk][row]  64 x PADF
    float* Kt = Qt + 64 * PADF;   // [kk][col]
    float* Vs = Kt + 64 * PADF;   // [key][dh]
    float* Pt = Vs + 64 * PADF;   // [key][row]

    const int head = blockIdx.y;
    const int qt   = blockIdx.x;
    const int tid  = threadIdx.x;
    const int ty   = tid >> 4;        // 0..15 -> S rows 4*ty..
    const int tx   = tid & 15;        // 0..15 -> S cols / dh 4*tx..
    const int lr   = tid >> 4;        // loader row base
    const int lc   = (tid & 15) << 2; // loader col (float4)

    // Load Q tile transposed: Qt[kk][row]
    {
        const float* qb = Q + (size_t)(qt * 64) * DIM + head * DHEAD;
#pragma unroll
        for (int i = 0; i < 4; i++) {
            int r = lr + i * 16;
            float4 qv = *reinterpret_cast<const float4*>(qb + (size_t)r * DIM + lc);
            Qt[(lc + 0) * PADF + r] = qv.x;
            Qt[(lc + 1) * PADF + r] = qv.y;
            Qt[(lc + 2) * PADF + r] = qv.z;
            Qt[(lc + 3) * PADF + r] = qv.w;
        }
    }

    float m_i[4], l_i[4], o[4][4];
#pragma unroll
    for (int i = 0; i < 4; i++) {
        m_i[i] = -1e30f; l_i[i] = 0.f;
#pragma unroll
        for (int j = 0; j < 4; j++) o[i][j] = 0.f;
    }

    for (int t = 0; t < SEQ / 64; t++) {
        __syncthreads();   // protect Kt/Vs overwrite vs previous PV, Q load on t=0
        const float* kb = K + (size_t)(t * 64) * DIM + head * DHEAD;
        const float* vb = V + (size_t)(t * 64) * DIM + head * DHEAD;
#pragma unroll
        for (int i = 0; i < 4; i++) {
            int r = lr + i * 16;
            float4 kv = *reinterpret_cast<const float4*>(kb + (size_t)r * DIM + lc);
            Kt[(lc + 0) * PADF + r] = kv.x;
            Kt[(lc + 1) * PADF + r] = kv.y;
            Kt[(lc + 2) * PADF + r] = kv.z;
            Kt[(lc + 3) * PADF + r] = kv.w;
            float4 vv = *reinterpret_cast<const float4*>(vb + (size_t)r * DIM + lc);
            *reinterpret_cast<float4*>(&Vs[r * PADF + lc]) = vv;
        }
        __syncthreads();

        // S = Q K^T (64x64x64), 4x4 microtile per thread
        float s[4][4];
#pragma unroll
        for (int i = 0; i < 4; i++)
#pragma unroll
            for (int j = 0; j < 4; j++) s[i][j] = 0.f;
#pragma unroll 8
        for (int kk = 0; kk < 64; kk++) {
            float4 qv = *reinterpret_cast<const float4*>(&Qt[kk * PADF + ty * 4]);
            float4 kv = *reinterpret_cast<const float4*>(&Kt[kk * PADF + tx * 4]);
            float qa[4] = {qv.x, qv.y, qv.z, qv.w};
            float ka[4] = {kv.x, kv.y, kv.z, kv.w};
#pragma unroll
            for (int i = 0; i < 4; i++)
#pragma unroll
                for (int j = 0; j < 4; j++)
                    s[i][j] = fmaf(qa[i], ka[j], s[i][j]);
        }

        // Online softmax update (rows owned by 16-lane groups)
#pragma unroll
        for (int i = 0; i < 4; i++) {
            float tm = -1e30f;
#pragma unroll
            for (int j = 0; j < 4; j++) {
                s[i][j] *= 0.125f;               // 1/sqrt(64)
                tm = fmaxf(tm, s[i][j]);
            }
            tm = fmaxf(tm, __shfl_xor_sync(0xffffffffu, tm, 8));
            tm = fmaxf(tm, __shfl_xor_sync(0xffffffffu, tm, 4));
            tm = fmaxf(tm, __shfl_xor_sync(0xffffffffu, tm, 2));
            tm = fmaxf(tm, __shfl_xor_sync(0xffffffffu, tm, 1));
            float mn   = fmaxf(m_i[i], tm);
            float corr = expf(m_i[i] - mn);
            float rs = 0.f;
#pragma unroll
            for (int j = 0; j < 4; j++) {
                float p = expf(s[i][j] - mn);
                s[i][j] = p;
                rs += p;
            }
            rs += __shfl_xor_sync(0xffffffffu, rs, 8);
            rs += __shfl_xor_sync(0xffffffffu, rs, 4);
            rs += __shfl_xor_sync(0xffffffffu, rs, 2);
            rs += __shfl_xor_sync(0xffffffffu, rs, 1);
            l_i[i] = l_i[i] * corr + rs;
            m_i[i] = mn;
#pragma unroll
            for (int j = 0; j < 4; j++) {
                o[i][j] *= corr;
                Pt[(tx * 4 + j) * PADF + ty * 4 + i] = s[i][j];
            }
        }
        __syncthreads();

        // O += P V
#pragma unroll 8
        for (int kk = 0; kk < 64; kk++) {
            float4 pv = *reinterpret_cast<const float4*>(&Pt[kk * PADF + ty * 4]);
            float4 vv = *reinterpret_cast<const float4*>(&Vs[kk * PADF + tx * 4]);
            float pa[4] = {pv.x, pv.y, pv.z, pv.w};
            float va[4] = {vv.x, vv.y, vv.z, vv.w};
#pragma unroll
            for (int i = 0; i < 4; i++)
#pragma unroll
                for (int j = 0; j < 4; j++)
                    o[i][j] = fmaf(pa[i], va[j], o[i][j]);
        }
    }

#pragma unroll
    for (int i = 0; i < 4; i++) {
        float inv = 1.f / l_i[i];
        float4 ov = make_float4(o[i][0] * inv, o[i][1] * inv,
                                o[i][2] * inv, o[i][3] * inv);
        *reinterpret_cast<float4*>(
            O + (size_t)(qt * 64 + ty * 4 + i) * DIM + head * DHEAD + tx * 4) = ov;
    }
}

// ---------------------------------------------------------------------------
// y = h + proj ; layernorm(y) * gamma + beta  (one block per row)
// ---------------------------------------------------------------------------
__global__ __launch_bounds__(256) void ln_kernel(const float* __restrict__ h,
                                                 const float* __restrict__ pr,
                                                 const float* __restrict__ gamma,
                                                 const float* __restrict__ beta,
                                                 float* __restrict__ out) {
    __shared__ float red[16];
    __shared__ float s_mu, s_rstd;
    int row = blockIdx.x, tid = threadIdx.x;
    int c0 = tid * 4;
    float4 hv = *reinterpret_cast<const float4*>(h  + (size_t)row * DIM + c0);
    float4 pv = *reinterpret_cast<const float4*>(pr + (size_t)row * DIM + c0);
    float y[4] = {hv.x + pv.x, hv.y + pv.y, hv.z + pv.z, hv.w + pv.w};
    float sum = y[0] + y[1] + y[2] + y[3];
    float sq  = y[0]*y[0] + y[1]*y[1] + y[2]*y[2] + y[3]*y[3];
#pragma unroll
    for (int off = 16; off; off >>= 1) {
        sum += __shfl_xor_sync(0xffffffffu, sum, off);
        sq  += __shfl_xor_sync(0xffffffffu, sq,  off);
    }
    int w = tid >> 5;
    if ((tid & 31) == 0) { red[w] = sum; red[8 + w] = sq; }
    __syncthreads();
    if (tid == 0) {
        float ts = 0.f, tq = 0.f;
        for (int i = 0; i < 8; i++) { ts += red[i]; tq += red[8 + i]; }
        float mu = ts / (float)DIM;
        s_mu   = mu;
        s_rstd = rsqrtf(tq / (float)DIM - mu * mu + 1e-5f);
    }
    __syncthreads();
    float4 gv = *reinterpret_cast<const float4*>(gamma + c0);
    float4 bv = *reinterpret_cast<const float4*>(beta  + c0);
    float mu = s_mu, rs = s_rstd;
    float4 ov;
    ov.x = (y[0] - mu) * rs * gv.x + bv.x;
    ov.y = (y[1] - mu) * rs * gv.y + bv.y;
    ov.z = (y[2] - mu) * rs * gv.z + bv.z;
    ov.w = (y[3] - mu) * rs * gv.w + bv.w;
    *reinterpret_cast<float4*>(out + (size_t)row * DIM + c0) = ov;
}

// ---------------------------------------------------------------------------
extern "C" void kernel_launch(void* const* d_in, const int* in_sizes, int n_in,
                              void* d_out, int out_size) {
    (void)in_sizes; (void)n_in; (void)out_size;
    const float* x     = (const float*)d_in[0];
    const float* Wq    = (const float*)d_in[1];
    const float* bq    = (const float*)d_in[2];
    const float* Wk    = (const float*)d_in[3];
    const float* bk    = (const float*)d_in[4];
    const float* Wv    = (const float*)d_in[5];
    const float* bv    = (const float*)d_in[6];
    const float* Wo    = (const float*)d_in[7];
    const float* bo    = (const float*)d_in[8];
    const float* gamma = (const float*)d_in[9];
    const float* beta  = (const float*)d_in[10];
    float* out = (float*)d_out;

    void* p;
    cudaGetSymbolAddress(&p, g_h);  float* h  = (float*)p;
    cudaGetSymbolAddress(&p, g_q);  float* q  = (float*)p;
    cudaGetSymbolAddress(&p, g_k);  float* k  = (float*)p;
    cudaGetSymbolAddress(&p, g_v);  float* v  = (float*)p;
    cudaGetSymbolAddress(&p, g_ao); float* ao = (float*)p;

    int smem_flash = 4 * 64 * PADF * (int)sizeof(float);   // 69632 B
    cudaFuncSetAttribute(flash_kernel,
                         cudaFuncAttributeMaxDynamicSharedMemorySize, smem_flash);

    add_pe_kernel<<<SEQ, 256>>>(x, h);

    dim3 gg(DIM / 128, SEQ / 128);
    sgemm_bias<<<gg, 256>>>(h, Wq, bq, q, SEQ, DIM, DIM);
    sgemm_bias<<<gg, 256>>>(h, Wk, bk, k, SEQ, DIM, DIM);
    sgemm_bias<<<gg, 256>>>(h, Wv, bv, v, SEQ, DIM, DIM);

    flash_kernel<<<dim3(SEQ / 64, NHEAD), 256, smem_flash>>>(q, k, v, ao);

    // reuse q as the output-projection scratch
    sgemm_bias<<<gg, 256>>>(ao, Wo, bo, q, SEQ, DIM, DIM);

    ln_kernel<<<SEQ, 256>>>(h, q, gamma, beta, out);
}

// round 2
// speedup vs baseline: 3.1310x; 3.1310x over previous
#include <cuda_runtime.h>
#include <cuda_bf16.h>
#include <math.h>
#include <stdint.h>

#define SEQ   4096
#define DIM   1024
#define NHEAD 16
#define DHEAD 64

typedef __nv_bfloat16 bf16;
typedef __nv_bfloat162 bf162;

// ---------------- scratch (no cudaMalloc allowed) ----------------
__device__ float g_h   [SEQ*DIM];      // x + pe (fp32, residual)
__device__ float g_proj[SEQ*DIM];      // final projection out (fp32)
__device__ bf16  g_hh[SEQ*DIM], g_hl[SEQ*DIM];
__device__ bf16  g_wh[4][DIM*DIM], g_wl[4][DIM*DIM];
__device__ bf16  g_qh[SEQ*DIM], g_ql[SEQ*DIM];
__device__ bf16  g_kh[SEQ*DIM], g_kl[SEQ*DIM];
__device__ bf16  g_vh[SEQ*DIM], g_vl[SEQ*DIM];
__device__ bf16  g_aoh[SEQ*DIM], g_aol[SEQ*DIM];

// ---------------- helpers ----------------
__device__ __forceinline__ uint32_t saddr(const void* p) {
    return (uint32_t)__cvta_generic_to_shared(p);
}
__device__ __forceinline__ float ex2f(float x) {
    float y; asm("ex2.approx.f32 %0, %1;" : "=f"(y) : "f"(x)); return y;
}
// swizzled element index, 64-col bf16 tile (col multiple of 8)
__device__ __forceinline__ int swzi64(int row, int col) {
    return row * 64 + ((((col >> 3) ^ row) & 7) << 3);
}
// swizzled element index, 128-col bf16 tile (col multiple of 8)
__device__ __forceinline__ int swzi128(int row, int col) {
    int cc = col >> 3;
    return row * 128 + (((cc & 8) | ((cc ^ row) & 7)) << 3);
}
__device__ __forceinline__ void ldsm4(uint32_t* r, uint32_t a) {
    asm volatile("ldmatrix.sync.aligned.m8n8.x4.shared.b16 {%0,%1,%2,%3},[%4];"
                 : "=r"(r[0]), "=r"(r[1]), "=r"(r[2]), "=r"(r[3]) : "r"(a));
}
__device__ __forceinline__ void ldsm4t(uint32_t* r, uint32_t a) {
    asm volatile("ldmatrix.sync.aligned.m8n8.x4.trans.shared.b16 {%0,%1,%2,%3},[%4];"
                 : "=r"(r[0]), "=r"(r[1]), "=r"(r[2]), "=r"(r[3]) : "r"(a));
}
__device__ __forceinline__ void mma16816(float* c, const uint32_t* a,
                                         uint32_t b0, uint32_t b1) {
    asm volatile(
        "mma.sync.aligned.m16n8k16.row.col.f32.bf16.bf16.f32 "
        "{%0,%1,%2,%3},{%4,%5,%6,%7},{%8,%9},{%0,%1,%2,%3};"
        : "+f"(c[0]), "+f"(c[1]), "+f"(c[2]), "+f"(c[3])
        : "r"(a[0]), "r"(a[1]), "r"(a[2]), "r"(a[3]), "r"(b0), "r"(b1));
}
__device__ __forceinline__ void split2(float a, float b, uint32_t& hi, uint32_t& lo) {
    bf16 ha = __float2bfloat16_rn(a), hb = __float2bfloat16_rn(b);
    bf162 hp; hp.x = ha; hp.y = hb;
    hi = *reinterpret_cast<uint32_t*>(&hp);
    bf162 lp = __floats2bfloat162_rn(a - __bfloat162float(ha),
                                     b - __bfloat162float(hb));
    lo = *reinterpret_cast<uint32_t*>(&lp);
}
__device__ __forceinline__ void store_split(bf16* Ch, bf16* Cl, size_t idx,
                                            float a, float b) {
    bf16 ha = __float2bfloat16_rn(a), hb = __float2bfloat16_rn(b);
    bf162 hp; hp.x = ha; hp.y = hb;
    *reinterpret_cast<bf162*>(Ch + idx) = hp;
    bf162 lp = __floats2bfloat162_rn(a - __bfloat162float(ha),
                                     b - __bfloat162float(hb));
    *reinterpret_cast<bf162*>(Cl + idx) = lp;
}

// ---------------- h = x + pe, plus hi/lo split ----------------
__global__ __launch_bounds__(256) void add_pe_split(const float* __restrict__ x,
                                                    float* __restrict__ h,
                                                    bf16* __restrict__ hh,
                                                    bf16* __restrict__ hl) {
    int row = blockIdx.x;
    int c0  = threadIdx.x * 4;
    const float kf = -9.210340371976184f / (float)DIM;
    float4 xv = *reinterpret_cast<const float4*>(x + (size_t)row * DIM + c0);
    float v[4] = {xv.x, xv.y, xv.z, xv.w};
    float o[4];
#pragma unroll
    for (int e = 0; e < 4; e++) {
        int c = c0 + e;
        float div = expf((float)(c & ~1) * kf);
        float arg = (float)row * div;
        o[e] = v[e] + ((c & 1) ? cosf(arg) : sinf(arg));
    }
    size_t base = (size_t)row * DIM + c0;
    *reinterpret_cast<float4*>(h + base) = make_float4(o[0], o[1], o[2], o[3]);
    store_split(hh, hl, base + 0, o[0], o[1]);
    store_split(hh, hl, base + 2, o[2], o[3]);
}

// ---------------- weight split ----------------
__global__ __launch_bounds__(256) void wsplit(const float* __restrict__ W,
                                              bf16* __restrict__ hi,
                                              bf16* __restrict__ lo) {
    int i = (blockIdx.x * 256 + threadIdx.x) * 4;
    float4 v = *reinterpret_cast<const float4*>(W + i);
    store_split(hi, lo, i + 0, v.x, v.y);
    store_split(hi, lo, i + 2, v.z, v.w);
}

// ---------------- split-bf16 GEMM: C[4096,1024] = A@B + bias ----------------
// grid (8, 32), 256 threads, 64KB dynamic smem
template <bool SPLIT_OUT>
__global__ __launch_bounds__(256, 2) void gemm_split(
    const bf16* __restrict__ Ah, const bf16* __restrict__ Al,
    const bf16* __restrict__ Bh, const bf16* __restrict__ Bl,
    const float* __restrict__ bias,
    bf16* __restrict__ Ch, bf16* __restrict__ Cl, float* __restrict__ Cf) {
    extern __shared__ bf16 smem[];
    bf16* sAh = smem;             // 128x64
    bf16* sAl = smem + 8192;
    bf16* sBh = smem + 16384;     // 64x128
    bf16* sBl = smem + 24576;

    const int tid  = threadIdx.x;
    const int warp = tid >> 5, lane = tid & 31;
    const int g = lane >> 2, t4 = lane & 3;
    const int wm = warp & 3, wn = warp >> 2;
    const int m0 = blockIdx.y * 128, n0 = blockIdx.x * 128;
    const int lr = lane & 7, sub = lane >> 3;

    float acc[2][8][4];
#pragma unroll
    for (int mt = 0; mt < 2; mt++)
#pragma unroll
        for (int nt = 0; nt < 8; nt++)
#pragma unroll
            for (int e = 0; e < 4; e++) acc[mt][nt][e] = 0.f;

    for (int kb = 0; kb < DIM / 64; kb++) {
        __syncthreads();
#pragma unroll
        for (int i = 0; i < 4; i++) {
            int id = tid + i * 256;
            int r = id >> 3, cc = id & 7;
            size_t ga = (size_t)(m0 + r) * DIM + kb * 64 + cc * 8;
            reinterpret_cast<uint4*>(sAh)[r * 8 + ((cc ^ r) & 7)] =
                *reinterpret_cast<const uint4*>(Ah + ga);
            reinterpret_cast<uint4*>(sAl)[r * 8 + ((cc ^ r) & 7)] =
                *reinterpret_cast<const uint4*>(Al + ga);
            int rb = id >> 4, cb = id & 15;
            size_t gb = (size_t)(kb * 64 + rb) * DIM + n0 + cb * 8;
            int sidx = rb * 16 + ((cb & 8) | ((cb ^ rb) & 7));
            reinterpret_cast<uint4*>(sBh)[sidx] =
                *reinterpret_cast<const uint4*>(Bh + gb);
            reinterpret_cast<uint4*>(sBl)[sidx] =
                *reinterpret_cast<const uint4*>(Bl + gb);
        }
        __syncthreads();
#pragma unroll
        for (int kk = 0; kk < 4; kk++) {
            uint32_t ah[2][4], al[2][4];
#pragma unroll
            for (int mt = 0; mt < 2; mt++) {
                int arow = wm * 32 + mt * 16 + lr + (sub & 1) * 8;
                int acol = kk * 16 + (sub >> 1) * 8;
                ldsm4(ah[mt], saddr(sAh + swzi64(arow, acol)));
                ldsm4(al[mt], saddr(sAl + swzi64(arow, acol)));
            }
#pragma unroll
            for (int ntt = 0; ntt < 4; ntt++) {
                int brow = kk * 16 + lr + (sub & 1) * 8;
                int bcol = wn * 64 + ntt * 16 + (sub >> 1) * 8;
                uint32_t bh[4], bl[4];
                ldsm4t(bh, saddr(sBh + swzi128(brow, bcol)));
                ldsm4t(bl, saddr(sBl + swzi128(brow, bcol)));
#pragma unroll
                for (int mt = 0; mt < 2; mt++) {
                    mma16816(acc[mt][2 * ntt], ah[mt], bh[0], bh[1]);
                    mma16816(acc[mt][2 * ntt], al[mt], bh[0], bh[1]);
                    mma16816(acc[mt][2 * ntt], ah[mt], bl[0], bl[1]);
                    mma16816(acc[mt][2 * ntt + 1], ah[mt], bh[2], bh[3]);
                    mma16816(acc[mt][2 * ntt + 1], al[mt], bh[2], bh[3]);
                    mma16816(acc[mt][2 * ntt + 1], ah[mt], bl[2], bl[3]);
                }
            }
        }
    }

#pragma unroll
    for (int mt = 0; mt < 2; mt++) {
#pragma unroll
        for (int nt = 0; nt < 8; nt++) {
            int row0 = m0 + wm * 32 + mt * 16 + g;
            int col  = n0 + wn * 64 + nt * 8 + t4 * 2;
            float b0 = bias[col], b1 = bias[col + 1];
            float v00 = acc[mt][nt][0] + b0, v01 = acc[mt][nt][1] + b1;
            float v10 = acc[mt][nt][2] + b0, v11 = acc[mt][nt][3] + b1;
            if (SPLIT_OUT) {
                store_split(Ch, Cl, (size_t)row0 * DIM + col, v00, v01);
                store_split(Ch, Cl, (size_t)(row0 + 8) * DIM + col, v10, v11);
            } else {
                *reinterpret_cast<float2*>(Cf + (size_t)row0 * DIM + col) =
                    make_float2(v00, v01);
                *reinterpret_cast<float2*>(Cf + (size_t)(row0 + 8) * DIM + col) =
                    make_float2(v10, v11);
            }
        }
    }
}

// ---------------- flash attention, split-bf16 mma ----------------
// grid (32 qtiles, 16 heads), 256 threads, 64KB dynamic smem
__global__ __launch_bounds__(256, 2) void flash_mma(
    const bf16* __restrict__ Qh, const bf16* __restrict__ Ql,
    const bf16* __restrict__ Kh, const bf16* __restrict__ Kl,
    const bf16* __restrict__ Vh, const bf16* __restrict__ Vl,
    bf16* __restrict__ Oh, bf16* __restrict__ Ol) {
    extern __shared__ bf16 smem[];
    bf16* sQh = smem;             // 128x64
    bf16* sQl = smem + 8192;
    bf16* sKh = smem + 16384;     // 64x64
    bf16* sKl = smem + 20480;
    bf16* sVh = smem + 24576;     // 64x64
    bf16* sVl = smem + 28672;

    const int tid   = threadIdx.x;
    const int warp  = tid >> 5, lane = tid & 31;
    const int g = lane >> 2, t4 = lane & 3;
    const int lr = lane & 7, sub = lane >> 3;
    const int rbase = warp * 16;
    const int head  = blockIdx.y;
    const int qt    = blockIdx.x;

    // load Q tile (hi/lo), swizzled
#pragma unroll
    for (int i = 0; i < 4; i++) {
        int id = tid + i * 256;
        int r = id >> 3, cc = id & 7;
        size_t gidx = (size_t)(qt * 128 + r) * DIM + head * DHEAD + cc * 8;
        reinterpret_cast<uint4*>(sQh)[r * 8 + ((cc ^ r) & 7)] =
            *reinterpret_cast<const uint4*>(Qh + gidx);
        reinterpret_cast<uint4*>(sQl)[r * 8 + ((cc ^ r) & 7)] =
            *reinterpret_cast<const uint4*>(Ql + gidx);
    }

    float m_i[2], l_i[2], o[8][4];
    m_i[0] = m_i[1] = -1e30f;
    l_i[0] = l_i[1] = 0.f;
#pragma unroll
    for (int nt = 0; nt < 8; nt++)
#pragma unroll
        for (int e = 0; e < 4; e++) o[nt][e] = 0.f;

    const float scale = 0.18033688011112042f;  // (1/8) * log2(e)

    for (int t = 0; t < SEQ / 64; t++) {
        __syncthreads();
#pragma unroll
        for (int i = 0; i < 2; i++) {
            int id = tid + i * 256;
            int r = id >> 3, cc = id & 7;
            size_t gidx = (size_t)(t * 64 + r) * DIM + head * DHEAD + cc * 8;
            int sidx = r * 8 + ((cc ^ r) & 7);
            reinterpret_cast<uint4*>(sKh)[sidx] =
                *reinterpret_cast<const uint4*>(Kh + gidx);
            reinterpret_cast<uint4*>(sKl)[sidx] =
                *reinterpret_cast<const uint4*>(Kl + gidx);
            reinterpret_cast<uint4*>(sVh)[sidx] =
                *reinterpret_cast<const uint4*>(Vh + gidx);
            reinterpret_cast<uint4*>(sVl)[sidx] =
                *reinterpret_cast<const uint4*>(Vl + gidx);
        }
        __syncthreads();

        // ---- S = Q K^T ----
        float s[8][4];
#pragma unroll
        for (int nt = 0; nt < 8; nt++)
#pragma unroll
            for (int e = 0; e < 4; e++) s[nt][e] = 0.f;
#pragma unroll
        for (int kk = 0; kk < 4; kk++) {
            uint32_t qh[4], ql[4];
            int arow = rbase + lr + (sub & 1) * 8;
            int acol = kk * 16 + (sub >> 1) * 8;
            ldsm4(qh, saddr(sQh + swzi64(arow, acol)));
            ldsm4(ql, saddr(sQl + swzi64(arow, acol)));
#pragma unroll
            for (int ntt = 0; ntt < 4; ntt++) {
                int brow = ntt * 16 + lr + (sub >> 1) * 8;
                int bcol = kk * 16 + (sub & 1) * 8;
                uint32_t kh[4], kl[4];
                ldsm4(kh, saddr(sKh + swzi64(brow, bcol)));
                ldsm4(kl, saddr(sKl + swzi64(brow, bcol)));
                mma16816(s[2 * ntt], qh, kh[0], kh[1]);
                mma16816(s[2 * ntt], ql, kh[0], kh[1]);
                mma16816(s[2 * ntt], qh, kl[0], kl[1]);
                mma16816(s[2 * ntt + 1], qh, kh[2], kh[3]);
                mma16816(s[2 * ntt + 1], ql, kh[2], kh[3]);
                mma16816(s[2 * ntt + 1], qh, kl[2], kl[3]);
            }
        }

        // ---- online softmax (scaled log2 domain) ----
#pragma unroll
        for (int r = 0; r < 2; r++) {
            float mx = -1e30f;
#pragma unroll
            for (int j = 0; j < 8; j++) {
                s[j][2 * r]     *= scale;
                s[j][2 * r + 1] *= scale;
                mx = fmaxf(mx, fmaxf(s[j][2 * r], s[j][2 * r + 1]));
            }
            mx = fmaxf(mx, __shfl_xor_sync(0xffffffffu, mx, 1));
            mx = fmaxf(mx, __shfl_xor_sync(0xffffffffu, mx, 2));
            float mnew = fmaxf(m_i[r], mx);
            float corr = ex2f(m_i[r] - mnew);
            m_i[r] = mnew;
            float rs = 0.f;
#pragma unroll
            for (int j = 0; j < 8; j++) {
                float p0 = ex2f(s[j][2 * r] - mnew);
                float p1 = ex2f(s[j][2 * r + 1] - mnew);
                s[j][2 * r] = p0; s[j][2 * r + 1] = p1;
                rs += p0 + p1;
            }
            rs += __shfl_xor_sync(0xffffffffu, rs, 1);
            rs += __shfl_xor_sync(0xffffffffu, rs, 2);
            l_i[r] = l_i[r] * corr + rs;
#pragma unroll
            for (int nt = 0; nt < 8; nt++) {
                o[nt][2 * r]     *= corr;
                o[nt][2 * r + 1] *= corr;
            }
        }

        // ---- O += P V  (P fragments built in registers) ----
#pragma unroll
        for (int kk = 0; kk < 4; kk++) {
            int j0 = 2 * kk, j1 = j0 + 1;
            uint32_t aH[4], aL[4];
            split2(s[j0][0], s[j0][1], aH[0], aL[0]);
            split2(s[j0][2], s[j0][3], aH[1], aL[1]);
            split2(s[j1][0], s[j1][1], aH[2], aL[2]);
            split2(s[j1][2], s[j1][3], aH[3], aL[3]);
#pragma unroll
            for (int ntt = 0; ntt < 4; ntt++) {
                int vrow = kk * 16 + lr + (sub & 1) * 8;
                int vcol = ntt * 16 + (sub >> 1) * 8;
                uint32_t vh[4], vl[4];
                ldsm4t(vh, saddr(sVh + swzi64(vrow, vcol)));
                ldsm4t(vl, saddr(sVl + swzi64(vrow, vcol)));
                mma16816(o[2 * ntt], aH, vh[0], vh[1]);
                mma16816(o[2 * ntt], aL, vh[0], vh[1]);
                mma16816(o[2 * ntt], aH, vl[0], vl[1]);
                mma16816(o[2 * ntt + 1], aH, vh[2], vh[3]);
                mma16816(o[2 * ntt + 1], aL, vh[2], vh[3]);
                mma16816(o[2 * ntt + 1], aH, vl[2], vl[3]);
            }
        }
    }

    // ---- epilogue: O /= l, split hi/lo, store ----
    float inv0 = 1.f / l_i[0], inv1 = 1.f / l_i[1];
#pragma unroll
    for (int nt = 0; nt < 8; nt++) {
        int row0 = qt * 128 + rbase + g;
        int col  = head * DHEAD + nt * 8 + t4 * 2;
        store_split(Oh, Ol, (size_t)row0 * DIM + col,
                    o[nt][0] * inv0, o[nt][1] * inv0);
        store_split(Oh, Ol, (size_t)(row0 + 8) * DIM + col,
                    o[nt][2] * inv1, o[nt][3] * inv1);
    }
}

// ---------------- residual + layernorm ----------------
__global__ __launch_bounds__(256) void ln_kernel(const float* __restrict__ h,
                                                 const float* __restrict__ pr,
                                                 const float* __restrict__ gamma,
                                                 const float* __restrict__ beta,
                                                 float* __restrict__ out) {
    __shared__ float red[16];
    __shared__ float s_mu, s_rstd;
    int row = blockIdx.x, tid = threadIdx.x;
    int c0 = tid * 4;
    float4 hv = *reinterpret_cast<const float4*>(h  + (size_t)row * DIM + c0);
    float4 pv = *reinterpret_cast<const float4*>(pr + (size_t)row * DIM + c0);
    float y[4] = {hv.x + pv.x, hv.y + pv.y, hv.z + pv.z, hv.w + pv.w};
    float sum = y[0] + y[1] + y[2] + y[3];
    float sq  = y[0]*y[0] + y[1]*y[1] + y[2]*y[2] + y[3]*y[3];
#pragma unroll
    for (int off = 16; off; off >>= 1) {
        sum += __shfl_xor_sync(0xffffffffu, sum, off);
        sq  += __shfl_xor_sync(0xffffffffu, sq,  off);
    }
    int w = tid >> 5;
    if ((tid & 31) == 0) { red[w] = sum; red[8 + w] = sq; }
    __syncthreads();
    if (tid == 0) {
        float ts = 0.f, tq = 0.f;
        for (int i = 0; i < 8; i++) { ts += red[i]; tq += red[8 + i]; }
        float mu = ts / (float)DIM;
        s_mu   = mu;
        s_rstd = rsqrtf(tq / (float)DIM - mu * mu + 1e-5f);
    }
    __syncthreads();
    float4 gv = *reinterpret_cast<const float4*>(gamma + c0);
    float4 bv = *reinterpret_cast<const float4*>(beta  + c0);
    float mu = s_mu, rs = s_rstd;
    float4 ov;
    ov.x = (y[0] - mu) * rs * gv.x + bv.x;
    ov.y = (y[1] - mu) * rs * gv.y + bv.y;
    ov.z = (y[2] - mu) * rs * gv.z + bv.z;
    ov.w = (y[3] - mu) * rs * gv.w + bv.w;
    *reinterpret_cast<float4*>(out + (size_t)row * DIM + c0) = ov;
}

// ---------------------------------------------------------------------------
extern "C" void kernel_launch(void* const* d_in, const int* in_sizes, int n_in,
                              void* d_out, int out_size) {
    (void)in_sizes; (void)n_in; (void)out_size;
    const float* x     = (const float*)d_in[0];
    const float* W[4]  = {(const float*)d_in[1], (const float*)d_in[3],
                          (const float*)d_in[5], (const float*)d_in[7]};
    const float* bq    = (const float*)d_in[2];
    const float* bk    = (const float*)d_in[4];
    const float* bv    = (const float*)d_in[6];
    const float* bo    = (const float*)d_in[8];
    const float* gamma = (const float*)d_in[9];
    const float* beta  = (const float*)d_in[10];
    float* out = (float*)d_out;

    void* p;
    cudaGetSymbolAddress(&p, g_h);    float* h    = (float*)p;
    cudaGetSymbolAddress(&p, g_proj); float* proj = (float*)p;
    cudaGetSymbolAddress(&p, g_hh);   bf16* hh = (bf16*)p;
    cudaGetSymbolAddress(&p, g_hl);   bf16* hl = (bf16*)p;
    cudaGetSymbolAddress(&p, g_wh);   bf16* wh = (bf16*)p;
    cudaGetSymbolAddress(&p, g_wl);   bf16* wl = (bf16*)p;
    cudaGetSymbolAddress(&p, g_qh);   bf16* qh = (bf16*)p;
    cudaGetSymbolAddress(&p, g_ql);   bf16* ql = (bf16*)p;
    cudaGetSymbolAddress(&p, g_kh);   bf16* kh = (bf16*)p;
    cudaGetSymbolAddress(&p, g_kl);   bf16* kl = (bf16*)p;
    cudaGetSymbolAddress(&p, g_vh);   bf16* vh = (bf16*)p;
    cudaGetSymbolAddress(&p, g_vl);   bf16* vl = (bf16*)p;
    cudaGetSymbolAddress(&p, g_aoh);  bf16* aoh = (bf16*)p;
    cudaGetSymbolAddress(&p, g_aol);  bf16* aol = (bf16*)p;

    const int SMEM = 65536;
    cudaFuncSetAttribute(gemm_split<true>,
                         cudaFuncAttributeMaxDynamicSharedMemorySize, SMEM);
    cudaFuncSetAttribute(gemm_split<false>,
                         cudaFuncAttributeMaxDynamicSharedMemorySize, SMEM);
    cudaFuncSetAttribute(flash_mma,
                         cudaFuncAttributeMaxDynamicSharedMemorySize, SMEM);

    add_pe_split<<<SEQ, 256>>>(x, h, hh, hl);
    for (int i = 0; i < 4; i++)
        wsplit<<<DIM * DIM / 1024, 256>>>(W[i], wh + (size_t)i * DIM * DIM,
                                          wl + (size_t)i * DIM * DIM);

    dim3 gg(DIM / 128, SEQ / 128);
    gemm_split<true><<<gg, 256, SMEM>>>(hh, hl, wh + 0 * (size_t)DIM * DIM,
                                        wl + 0 * (size_t)DIM * DIM, bq,
                                        qh, ql, nullptr);
    gemm_split<true><<<gg, 256, SMEM>>>(hh, hl, wh + 1 * (size_t)DIM * DIM,
                                        wl + 1 * (size_t)DIM * DIM, bk,
                                        kh, kl, nullptr);
    gemm_split<true><<<gg, 256, SMEM>>>(hh, hl, wh + 2 * (size_t)DIM * DIM,
                                        wl + 2 * (size_t)DIM * DIM, bv,
                                        vh, vl, nullptr);

    flash_mma<<<dim3(SEQ / 128, NHEAD), 256, SMEM>>>(qh, ql, kh, kl, vh, vl,
                                                     aoh, aol);

    gemm_split<false><<<gg, 256, SMEM>>>(aoh, aol, wh + 3 * (size_t)DIM * DIM,
                                         wl + 3 * (size_t)DIM * DIM, bo,
                                         nullptr, nullptr, proj);

    ln_kernel<<<SEQ, 256>>>(h, proj, gamma, beta, out);
}

// round 4
// speedup vs baseline: 3.9500x; 1.2616x over previous
#include <cuda_runtime.h>
#include <cuda_bf16.h>
#include <math.h>
#include <stdint.h>

#define SEQ   4096
#define DIM   1024
#define NHEAD 16
#define DHEAD 64

typedef __nv_bfloat16 bf16;
typedef __nv_bfloat162 bf162;

// ---------------- scratch (no cudaMalloc allowed) ----------------
__device__ float g_h   [SEQ*DIM];      // x + pe (fp32, residual)
__device__ float g_proj[SEQ*DIM];      // final projection out (fp32)
__device__ bf16  g_hh[SEQ*DIM], g_hl[SEQ*DIM];
__device__ bf16  g_wh[4][DIM*DIM], g_wl[4][DIM*DIM];   // TRANSPOSED [N,K]
__device__ bf16  g_qh[SEQ*DIM], g_ql[SEQ*DIM];
__device__ bf16  g_kh[SEQ*DIM], g_kl[SEQ*DIM];
__device__ bf16  g_vh[SEQ*DIM], g_vl[SEQ*DIM];
__device__ bf16  g_aoh[SEQ*DIM], g_aol[SEQ*DIM];

// ---------------- helpers ----------------
__device__ __forceinline__ uint32_t saddr(const void* p) {
    return (uint32_t)__cvta_generic_to_shared(p);
}
__device__ __forceinline__ float ex2f(float x) {
    float y; asm("ex2.approx.f32 %0, %1;" : "=f"(y) : "f"(x)); return y;
}
// swizzled element index, 64-col bf16 tile (8 quads/row)
__device__ __forceinline__ int swzi64(int row, int col) {
    return row * 64 + ((((col >> 3) ^ row) & 7) << 3);
}
// swizzled element index, 128-col bf16 tile (16 quads/row)
__device__ __forceinline__ int swzi128(int row, int col) {
    int cc = col >> 3;
    return row * 128 + (((cc & 8) | ((cc ^ row) & 7)) << 3);
}
__device__ __forceinline__ void ldsm4(uint32_t* r, uint32_t a) {
    asm volatile("ldmatrix.sync.aligned.m8n8.x4.shared.b16 {%0,%1,%2,%3},[%4];"
                 : "=r"(r[0]), "=r"(r[1]), "=r"(r[2]), "=r"(r[3]) : "r"(a));
}
__device__ __forceinline__ void ldsm4t(uint32_t* r, uint32_t a) {
    asm volatile("ldmatrix.sync.aligned.m8n8.x4.trans.shared.b16 {%0,%1,%2,%3},[%4];"
                 : "=r"(r[0]), "=r"(r[1]), "=r"(r[2]), "=r"(r[3]) : "r"(a));
}
__device__ __forceinline__ void mma16816(float* c, const uint32_t* a,
                                         uint32_t b0, uint32_t b1) {
    asm volatile(
        "mma.sync.aligned.m16n8k16.row.col.f32.bf16.bf16.f32 "
        "{%0,%1,%2,%3},{%4,%5,%6,%7},{%8,%9},{%0,%1,%2,%3};"
        : "+f"(c[0]), "+f"(c[1]), "+f"(c[2]), "+f"(c[3])
        : "r"(a[0]), "r"(a[1]), "r"(a[2]), "r"(a[3]), "r"(b0), "r"(b1));
}
__device__ __forceinline__ uint32_t packbf(float a, float b) {
    bf162 t = __floats2bfloat162_rn(a, b);
    return *reinterpret_cast<uint32_t*>(&t);
}
__device__ __forceinline__ void store_split(bf16* Ch, bf16* Cl, size_t idx,
                                            float a, float b) {
    bf16 ha = __float2bfloat16_rn(a), hb = __float2bfloat16_rn(b);
    bf162 hp; hp.x = ha; hp.y = hb;
    *reinterpret_cast<bf162*>(Ch + idx) = hp;
    bf162 lp = __floats2bfloat162_rn(a - __bfloat162float(ha),
                                     b - __bfloat162float(hb));
    *reinterpret_cast<bf162*>(Cl + idx) = lp;
}
__device__ __forceinline__ void cpasync16(void* dst, const void* src) {
    asm volatile("cp.async.cg.shared.global [%0], [%1], 16;"
                 :: "r"(saddr(dst)), "l"(src));
}
__device__ __forceinline__ void cp_commit() {
    asm volatile("cp.async.commit_group;" ::: "memory");
}
template <int N> __device__ __forceinline__ void cp_wait() {
    asm volatile("cp.async.wait_group %0;" :: "n"(N) : "memory");
}

// ---------------- h = x + pe, plus hi/lo split ----------------
__global__ __launch_bounds__(256) void add_pe_split(const float* __restrict__ x,
                                                    float* __restrict__ h,
                                                    bf16* __restrict__ hh,
                                                    bf16* __restrict__ hl) {
    int row = blockIdx.x;
    int c0  = threadIdx.x * 4;
    const float kf = -9.210340371976184f / (float)DIM;
    float4 xv = *reinterpret_cast<const float4*>(x + (size_t)row * DIM + c0);
    float v[4] = {xv.x, xv.y, xv.z, xv.w};
    float o[4];
#pragma unroll
    for (int e = 0; e < 4; e++) {
        int c = c0 + e;
        float div = expf((float)(c & ~1) * kf);
        float arg = (float)row * div;
        o[e] = v[e] + ((c & 1) ? cosf(arg) : sinf(arg));
    }
    size_t base = (size_t)row * DIM + c0;
    *reinterpret_cast<float4*>(h + base) = make_float4(o[0], o[1], o[2], o[3]);
    store_split(hh, hl, base + 0, o[0], o[1]);
    store_split(hh, hl, base + 2, o[2], o[3]);
}

// ---------------- weight split + transpose: Wt[n,k] = W[k,n] ----------------
__global__ __launch_bounds__(256) void wsplit_t(const float* __restrict__ W,
                                                bf16* __restrict__ hi,
                                                bf16* __restrict__ lo) {
    __shared__ float t[32][33];
    int k0 = blockIdx.x * 32, n0 = blockIdx.y * 32;
    int tx = threadIdx.x, ty = threadIdx.y;
#pragma unroll
    for (int j = 0; j < 4; j++)
        t[ty + 8 * j][tx] = W[(size_t)(k0 + ty + 8 * j) * DIM + n0 + tx];
    __syncthreads();
#pragma unroll
    for (int j = 0; j < 4; j++) {
        int n = n0 + ty + 8 * j, k = k0 + tx;
        float v = t[tx][ty + 8 * j];
        bf16 h = __float2bfloat16_rn(v);
        hi[(size_t)n * DIM + k] = h;
        lo[(size_t)n * DIM + k] = __float2bfloat16_rn(v - __bfloat162float(h));
    }
}

// ---------------- split-bf16 GEMM, cp.async 2-stage pipeline ----------------
// C[4096,1024] = A[M,K] @ Wt[N,K]^T + bias. K-chunk 32 (hi cols 0-31, lo 32-63).
// Stage = A(128x64) + B(128x64) = 32KB; 2 stages; grid (8,32), 256 thr, occ 2.
#define GKCH 32

template <bool SPLIT_OUT>
__global__ __launch_bounds__(256, 2) void gemm_cp(
    const bf16* __restrict__ Ah, const bf16* __restrict__ Al,
    const bf16* __restrict__ Bh, const bf16* __restrict__ Bl,
    const float* __restrict__ bias,
    bf16* __restrict__ Ch, bf16* __restrict__ Cl, float* __restrict__ Cf) {
    extern __shared__ bf16 sm[];
    const int tid  = threadIdx.x;
    const int warp = tid >> 5, lane = tid & 31;
    const int g = lane >> 2, t4 = lane & 3;
    const int lr = lane & 7, sub = lane >> 3;
    const int wm = warp & 3, wn = warp >> 2;
    const int m0 = blockIdx.y * 128, n0 = blockIdx.x * 128;

    auto load_chunk = [&](int kb, int st) {
        bf16* sA = sm + st * 16384;
        bf16* sB = sA + 8192;
#pragma unroll
        for (int i = 0; i < 4; i++) {
            int id = tid + i * 256;          // 0..1023
            int r = id >> 3, cc = id & 7;
            int sidx = (r * 8 + ((cc ^ r) & 7)) * 8;
            const bf16* sa = (cc < 4)
                ? Ah + (size_t)(m0 + r) * DIM + kb * GKCH + cc * 8
                : Al + (size_t)(m0 + r) * DIM + kb * GKCH + (cc - 4) * 8;
            cpasync16(sA + sidx, sa);
            const bf16* sb = (cc < 4)
                ? Bh + (size_t)(n0 + r) * DIM + kb * GKCH + cc * 8
                : Bl + (size_t)(n0 + r) * DIM + kb * GKCH + (cc - 4) * 8;
            cpasync16(sB + sidx, sb);
        }
    };

    float acc[2][8][4];
#pragma unroll
    for (int mt = 0; mt < 2; mt++)
#pragma unroll
        for (int nt = 0; nt < 8; nt++)
#pragma unroll
            for (int e = 0; e < 4; e++) acc[mt][nt][e] = 0.f;

    load_chunk(0, 0);
    cp_commit();

    const int NCH = DIM / GKCH;          // 32
    for (int kb = 0; kb < NCH; kb++) {
        int st = kb & 1;
        if (kb + 1 < NCH) { load_chunk(kb + 1, st ^ 1); cp_commit(); cp_wait<1>(); }
        else              { cp_wait<0>(); }
        __syncthreads();
        bf16* sA = sm + st * 16384;
        bf16* sB = sA + 8192;
#pragma unroll
        for (int kk = 0; kk < 2; kk++) {
            uint32_t ah[2][4], al[2][4];
#pragma unroll
            for (int mt = 0; mt < 2; mt++) {
                int ar = wm * 32 + mt * 16 + lr + (sub & 1) * 8;
                int ac = kk * 16 + (sub >> 1) * 8;
                ldsm4(ah[mt], saddr(sA + swzi64(ar, ac)));
                ldsm4(al[mt], saddr(sA + swzi64(ar, ac + 32)));
            }
#pragma unroll
            for (int ntt = 0; ntt < 4; ntt++) {
                int br = wn * 64 + ntt * 16 + lr + (sub >> 1) * 8;
                int bc = kk * 16 + (sub & 1) * 8;
                uint32_t bh[4], bl[4];
                ldsm4(bh, saddr(sB + swzi64(br, bc)));
                ldsm4(bl, saddr(sB + swzi64(br, bc + 32)));
#pragma unroll
                for (int mt = 0; mt < 2; mt++) {
                    mma16816(acc[mt][2 * ntt], ah[mt], bh[0], bh[1]);
                    mma16816(acc[mt][2 * ntt], al[mt], bh[0], bh[1]);
                    mma16816(acc[mt][2 * ntt], ah[mt], bl[0], bl[1]);
                    mma16816(acc[mt][2 * ntt + 1], ah[mt], bh[2], bh[3]);
                    mma16816(acc[mt][2 * ntt + 1], al[mt], bh[2], bh[3]);
                    mma16816(acc[mt][2 * ntt + 1], ah[mt], bl[2], bl[3]);
                }
            }
        }
        __syncthreads();
    }

#pragma unroll
    for (int mt = 0; mt < 2; mt++) {
#pragma unroll
        for (int nt = 0; nt < 8; nt++) {
            int row0 = m0 + wm * 32 + mt * 16 + g;
            int col  = n0 + wn * 64 + nt * 8 + t4 * 2;
            float b0 = bias[col], b1 = bias[col + 1];
            float v00 = acc[mt][nt][0] + b0, v01 = acc[mt][nt][1] + b1;
            float v10 = acc[mt][nt][2] + b0, v11 = acc[mt][nt][3] + b1;
            if (SPLIT_OUT) {
                store_split(Ch, Cl, (size_t)row0 * DIM + col, v00, v01);
                store_split(Ch, Cl, (size_t)(row0 + 8) * DIM + col, v10, v11);
            } else {
                *reinterpret_cast<float2*>(Cf + (size_t)row0 * DIM + col) =
                    make_float2(v00, v01);
                *reinterpret_cast<float2*>(Cf + (size_t)(row0 + 8) * DIM + col) =
                    make_float2(v10, v11);
            }
        }
    }
}

// ---------------- flash attention: 2-product S & PV, cp.async pipeline -------
// S = Qh*(Kh+Kl); O = Ph*(Vh+Vl).  Q tile 128x64 (hi only, 16KB).
// KV stage: K 64x128 (hi|lo) + V 64x128 = 32KB; 2 stages. Total 80KB, occ 2.
__global__ __launch_bounds__(256, 2) void flash_cp(
    const bf16* __restrict__ Qh,
    const bf16* __restrict__ Kh, const bf16* __restrict__ Kl,
    const bf16* __restrict__ Vh, const bf16* __restrict__ Vl,
    bf16* __restrict__ Oh, bf16* __restrict__ Ol) {
    extern __shared__ bf16 sm[];
    bf16* sQ = sm;                       // 128 x 64

    const int tid  = threadIdx.x;
    const int warp = tid >> 5, lane = tid & 31;
    const int g = lane >> 2, t4 = lane & 3;
    const int lr = lane & 7, sub = lane >> 3;
    const int rbase = warp * 16;
    const int head  = blockIdx.y;
    const int qt    = blockIdx.x;

    // Q (hi only) via cp.async — included in group 0
    {
        const bf16* qb = Qh + (size_t)(qt * 128) * DIM + head * DHEAD;
#pragma unroll
        for (int i = 0; i < 4; i++) {
            int id = tid + i * 256;
            int r = id >> 3, cc = id & 7;
            cpasync16(sQ + (r * 64 + ((cc ^ r) & 7) * 8),
                      qb + (size_t)r * DIM + cc * 8);
        }
    }
    auto load_kv = [&](int t, int st) {
        bf16* sK = sm + 8192 + st * 16384;
        bf16* sV = sK + 8192;
        const size_t base = (size_t)(t * 64) * DIM + head * DHEAD;
#pragma unroll
        for (int i = 0; i < 4; i++) {
            int id = tid + i * 256;          // 0..1023 quad ids
            int r = id >> 4, cc = id & 15;
            int sidx = (r * 16 + ((cc & 8) | ((cc ^ r) & 7))) * 8;
            const bf16* sk = (cc < 8)
                ? Kh + base + (size_t)r * DIM + cc * 8
                : Kl + base + (size_t)r * DIM + (cc - 8) * 8;
            cpasync16(sK + sidx, sk);
            const bf16* sv = (cc < 8)
                ? Vh + base + (size_t)r * DIM + cc * 8
                : Vl + base + (size_t)r * DIM + (cc - 8) * 8;
            cpasync16(sV + sidx, sv);
        }
    };

    float m_i[2], l_i[2], o[8][4];
    m_i[0] = m_i[1] = -1e30f;
    l_i[0] = l_i[1] = 0.f;
#pragma unroll
    for (int nt = 0; nt < 8; nt++)
#pragma unroll
        for (int e = 0; e < 4; e++) o[nt][e] = 0.f;

    const float scale = 0.18033688011112042f;   // (1/8)*log2(e)
    const int NT = SEQ / 64;

    load_kv(0, 0);
    cp_commit();

    for (int t = 0; t < NT; t++) {
        int st = t & 1;
        if (t + 1 < NT) { load_kv(t + 1, st ^ 1); cp_commit(); cp_wait<1>(); }
        else            { cp_wait<0>(); }
        __syncthreads();
        bf16* sK = sm + 8192 + st * 16384;
        bf16* sV = sK + 8192;

        // ---- S = Qh * K ----
        float s[8][4];
#pragma unroll
        for (int nt = 0; nt < 8; nt++)
#pragma unroll
            for (int e = 0; e < 4; e++) s[nt][e] = 0.f;
#pragma unroll
        for (int kk = 0; kk < 4; kk++) {
            uint32_t qf[4];
            ldsm4(qf, saddr(sQ + swzi64(rbase + lr + (sub & 1) * 8,
                                        kk * 16 + (sub >> 1) * 8)));
#pragma unroll
            for (int ntt = 0; ntt < 4; ntt++) {
                int krow = ntt * 16 + lr + (sub >> 1) * 8;
                int kcol = kk * 16 + (sub & 1) * 8;
                uint32_t khf[4], klf[4];
                ldsm4(khf, saddr(sK + swzi128(krow, kcol)));
                ldsm4(klf, saddr(sK + swzi128(krow, kcol + 64)));
                mma16816(s[2 * ntt],     qf, khf[0], khf[1]);
                mma16816(s[2 * ntt],     qf, klf[0], klf[1]);
                mma16816(s[2 * ntt + 1], qf, khf[2], khf[3]);
                mma16816(s[2 * ntt + 1], qf, klf[2], klf[3]);
            }
        }

        // ---- online softmax (log2 domain) ----
#pragma unroll
        for (int r = 0; r < 2; r++) {
            float mx = -1e30f;
#pragma unroll
            for (int j = 0; j < 8; j++) {
                s[j][2 * r]     *= scale;
                s[j][2 * r + 1] *= scale;
                mx = fmaxf(mx, fmaxf(s[j][2 * r], s[j][2 * r + 1]));
            }
            mx = fmaxf(mx, __shfl_xor_sync(0xffffffffu, mx, 1));
            mx = fmaxf(mx, __shfl_xor_sync(0xffffffffu, mx, 2));
            float mnew = fmaxf(m_i[r], mx);
            float corr = ex2f(m_i[r] - mnew);
            m_i[r] = mnew;
            float rs = 0.f;
#pragma unroll
            for (int j = 0; j < 8; j++) {
                float p0 = ex2f(s[j][2 * r] - mnew);
                float p1 = ex2f(s[j][2 * r + 1] - mnew);
                s[j][2 * r] = p0; s[j][2 * r + 1] = p1;
                rs += p0 + p1;
            }
            rs += __shfl_xor_sync(0xffffffffu, rs, 1);
            rs += __shfl_xor_sync(0xffffffffu, rs, 2);
            l_i[r] = l_i[r] * corr + rs;
#pragma unroll
            for (int nt = 0; nt < 8; nt++) {
                o[nt][2 * r]     *= corr;
                o[nt][2 * r + 1] *= corr;
            }
        }

        // ---- O += Ph * V ----
#pragma unroll
        for (int kk = 0; kk < 4; kk++) {
            int j0 = 2 * kk, j1 = j0 + 1;
            uint32_t aH[4];
            aH[0] = packbf(s[j0][0], s[j0][1]);
            aH[1] = packbf(s[j0][2], s[j0][3]);
            aH[2] = packbf(s[j1][0], s[j1][1]);
            aH[3] = packbf(s[j1][2], s[j1][3]);
#pragma unroll
            for (int ntt = 0; ntt < 4; ntt++) {
                int vrow = kk * 16 + lr + (sub & 1) * 8;
                int vcol = ntt * 16 + (sub >> 1) * 8;
                uint32_t vhf[4], vlf[4];
                ldsm4t(vhf, saddr(sV + swzi128(vrow, vcol)));
                ldsm4t(vlf, saddr(sV + swzi128(vrow, vcol + 64)));
                mma16816(o[2 * ntt],     aH, vhf[0], vhf[1]);
                mma16816(o[2 * ntt],     aH, vlf[0], vlf[1]);
                mma16816(o[2 * ntt + 1], aH, vhf[2], vhf[3]);
                mma16816(o[2 * ntt + 1], aH, vlf[2], vlf[3]);
            }
        }
        __syncthreads();
    }

    float inv0 = 1.f / l_i[0], inv1 = 1.f / l_i[1];
#pragma unroll
    for (int nt = 0; nt < 8; nt++) {
        int row0 = qt * 128 + rbase + g;
        int col  = head * DHEAD + nt * 8 + t4 * 2;
        store_split(Oh, Ol, (size_t)row0 * DIM + col,
                    o[nt][0] * inv0, o[nt][1] * inv0);
        store_split(Oh, Ol, (size_t)(row0 + 8) * DIM + col,
                    o[nt][2] * inv1, o[nt][3] * inv1);
    }
}

// ---------------- residual + layernorm ----------------
__global__ __launch_bounds__(256) void ln_kernel(const float* __restrict__ h,
                                                 const float* __restrict__ pr,
                                                 const float* __restrict__ gamma,
                                                 const float* __restrict__ beta,
                                                 float* __restrict__ out) {
    __shared__ float red[16];
    __shared__ float s_mu, s_rstd;
    int row = blockIdx.x, tid = threadIdx.x;
    int c0 = tid * 4;
    float4 hv = *reinterpret_cast<const float4*>(h  + (size_t)row * DIM + c0);
    float4 pv = *reinterpret_cast<const float4*>(pr + (size_t)row * DIM + c0);
    float y[4] = {hv.x + pv.x, hv.y + pv.y, hv.z + pv.z, hv.w + pv.w};
    float sum = y[0] + y[1] + y[2] + y[3];
    float sq  = y[0]*y[0] + y[1]*y[1] + y[2]*y[2] + y[3]*y[3];
#pragma unroll
    for (int off = 16; off; off >>= 1) {
        sum += __shfl_xor_sync(0xffffffffu, sum, off);
        sq  += __shfl_xor_sync(0xffffffffu, sq,  off);
    }
    int w = tid >> 5;
    if ((tid & 31) == 0) { red[w] = sum; red[8 + w] = sq; }
    __syncthreads();
    if (tid == 0) {
        float ts = 0.f, tq = 0.f;
        for (int i = 0; i < 8; i++) { ts += red[i]; tq += red[8 + i]; }
        float mu = ts / (float)DIM;
        s_mu   = mu;
        s_rstd = rsqrtf(tq / (float)DIM - mu * mu + 1e-5f);
    }
    __syncthreads();
    float4 gv = *reinterpret_cast<const float4*>(gamma + c0);
    float4 bv = *reinterpret_cast<const float4*>(beta  + c0);
    float mu = s_mu, rs = s_rstd;
    float4 ov;
    ov.x = (y[0] - mu) * rs * gv.x + bv.x;
    ov.y = (y[1] - mu) * rs * gv.y + bv.y;
    ov.z = (y[2] - mu) * rs * gv.z + bv.z;
    ov.w = (y[3] - mu) * rs * gv.w + bv.w;
    *reinterpret_cast<float4*>(out + (size_t)row * DIM + c0) = ov;
}

// ---------------------------------------------------------------------------
extern "C" void kernel_launch(void* const* d_in, const int* in_sizes, int n_in,
                              void* d_out, int out_size) {
    (void)in_sizes; (void)n_in; (void)out_size;
    const float* x     = (const float*)d_in[0];
    const float* W[4]  = {(const float*)d_in[1], (const float*)d_in[3],
                          (const float*)d_in[5], (const float*)d_in[7]};
    const float* bq    = (const float*)d_in[2];
    const float* bk    = (const float*)d_in[4];
    const float* bv    = (const float*)d_in[6];
    const float* bo    = (const float*)d_in[8];
    const float* gamma = (const float*)d_in[9];
    const float* beta  = (const float*)d_in[10];
    float* out = (float*)d_out;

    void* p;
    cudaGetSymbolAddress(&p, g_h);    float* h    = (float*)p;
    cudaGetSymbolAddress(&p, g_proj); float* proj = (float*)p;
    cudaGetSymbolAddress(&p, g_hh);   bf16* hh = (bf16*)p;
    cudaGetSymbolAddress(&p, g_hl);   bf16* hl = (bf16*)p;
    cudaGetSymbolAddress(&p, g_wh);   bf16* wh = (bf16*)p;
    cudaGetSymbolAddress(&p, g_wl);   bf16* wl = (bf16*)p;
    cudaGetSymbolAddress(&p, g_qh);   bf16* qh = (bf16*)p;
    cudaGetSymbolAddress(&p, g_ql);   bf16* ql = (bf16*)p;
    cudaGetSymbolAddress(&p, g_kh);   bf16* kh = (bf16*)p;
    cudaGetSymbolAddress(&p, g_kl);   bf16* kl = (bf16*)p;
    cudaGetSymbolAddress(&p, g_vh);   bf16* vh = (bf16*)p;
    cudaGetSymbolAddress(&p, g_vl);   bf16* vl = (bf16*)p;
    cudaGetSymbolAddress(&p, g_aoh);  bf16* aoh = (bf16*)p;
    cudaGetSymbolAddress(&p, g_aol);  bf16* aol = (bf16*)p;

    const int SMEM_G = 65536;            // 2 stages x 32KB
    const int SMEM_F = 81920;            // Q 16KB + 2 stages x 32KB
    cudaFuncSetAttribute(gemm_cp<true>,
                         cudaFuncAttributeMaxDynamicSharedMemorySize, SMEM_G);
    cudaFuncSetAttribute(gemm_cp<false>,
                         cudaFuncAttributeMaxDynamicSharedMemorySize, SMEM_G);
    cudaFuncSetAttribute(flash_cp,
                         cudaFuncAttributeMaxDynamicSharedMemorySize, SMEM_F);

    add_pe_split<<<SEQ, 256>>>(x, h, hh, hl);
    dim3 tg(DIM / 32, DIM / 32);
    for (int i = 0; i < 4; i++)
        wsplit_t<<<tg, dim3(32, 8)>>>(W[i], wh + (size_t)i * DIM * DIM,
                                      wl + (size_t)i * DIM * DIM);

    dim3 gg(DIM / 128, SEQ / 128);
    gemm_cp<true><<<gg, 256, SMEM_G>>>(hh, hl, wh + 0 * (size_t)DIM * DIM,
                                       wl + 0 * (size_t)DIM * DIM, bq,
                                       qh, ql, nullptr);
    gemm_cp<true><<<gg, 256, SMEM_G>>>(hh, hl, wh + 1 * (size_t)DIM * DIM,
                                       wl + 1 * (size_t)DIM * DIM, bk,
                                       kh, kl, nullptr);
    gemm_cp<true><<<gg, 256, SMEM_G>>>(hh, hl, wh + 2 * (size_t)DIM * DIM,
                                       wl + 2 * (size_t)DIM * DIM, bv,
                                       vh, vl, nullptr);

    flash_cp<<<dim3(SEQ / 128, NHEAD), 256, SMEM_F>>>(qh, kh, kl, vh, vl,
                                                      aoh, aol);

    gemm_cp<false><<<gg, 256, SMEM_G>>>(aoh, aol, wh + 3 * (size_t)DIM * DIM,
                                        wl + 3 * (size_t)DIM * DIM, bo,
                                        nullptr, nullptr, proj);

    ln_kernel<<<SEQ, 256>>>(h, proj, gamma, beta, out);
}

// round 6
// speedup vs baseline: 5.1013x; 1.2915x over previous
#include <cuda_runtime.h>
#include <cuda_bf16.h>
#include <cuda_fp16.h>
#include <math.h>
#include <stdint.h>

#define SEQ   4096
#define DIM   1024
#define NHEAD 16
#define DHEAD 64

typedef __nv_bfloat16 bf16;
typedef __nv_bfloat162 bf162;

// ---------------- scratch (no cudaMalloc allowed) ----------------
__device__ float  g_h   [SEQ*DIM];     // x + pe (fp32, residual)
__device__ float  g_proj[SEQ*DIM];     // final projection out (fp32)
__device__ bf16   g_hh[SEQ*DIM], g_hl[SEQ*DIM];
__device__ bf16   g_wh[4][DIM*DIM], g_wl[4][DIM*DIM];   // TRANSPOSED [N,K]
__device__ __half g_qf[SEQ*DIM], g_kf[SEQ*DIM], g_vf[SEQ*DIM];
__device__ bf16   g_aoh[SEQ*DIM], g_aol[SEQ*DIM];

// ---------------- helpers ----------------
__device__ __forceinline__ uint32_t saddr(const void* p) {
    return (uint32_t)__cvta_generic_to_shared(p);
}
__device__ __forceinline__ float ex2f(float x) {
    float y; asm("ex2.approx.f32 %0, %1;" : "=f"(y) : "f"(x)); return y;
}
__device__ __forceinline__ int swzi64(int row, int col) {
    return row * 64 + ((((col >> 3) ^ row) & 7) << 3);
}
__device__ __forceinline__ void ldsm4(uint32_t* r, uint32_t a) {
    asm volatile("ldmatrix.sync.aligned.m8n8.x4.shared.b16 {%0,%1,%2,%3},[%4];"
                 : "=r"(r[0]), "=r"(r[1]), "=r"(r[2]), "=r"(r[3]) : "r"(a));
}
__device__ __forceinline__ void ldsm4t(uint32_t* r, uint32_t a) {
    asm volatile("ldmatrix.sync.aligned.m8n8.x4.trans.shared.b16 {%0,%1,%2,%3},[%4];"
                 : "=r"(r[0]), "=r"(r[1]), "=r"(r[2]), "=r"(r[3]) : "r"(a));
}
__device__ __forceinline__ void mma_bf(float* c, const uint32_t* a,
                                       uint32_t b0, uint32_t b1) {
    asm volatile(
        "mma.sync.aligned.m16n8k16.row.col.f32.bf16.bf16.f32 "
        "{%0,%1,%2,%3},{%4,%5,%6,%7},{%8,%9},{%0,%1,%2,%3};"
        : "+f"(c[0]), "+f"(c[1]), "+f"(c[2]), "+f"(c[3])
        : "r"(a[0]), "r"(a[1]), "r"(a[2]), "r"(a[3]), "r"(b0), "r"(b1));
}
__device__ __forceinline__ void mma_hf(float* c, const uint32_t* a,
                                       uint32_t b0, uint32_t b1) {
    asm volatile(
        "mma.sync.aligned.m16n8k16.row.col.f32.f16.f16.f32 "
        "{%0,%1,%2,%3},{%4,%5,%6,%7},{%8,%9},{%0,%1,%2,%3};"
        : "+f"(c[0]), "+f"(c[1]), "+f"(c[2]), "+f"(c[3])
        : "r"(a[0]), "r"(a[1]), "r"(a[2]), "r"(a[3]), "r"(b0), "r"(b1));
}
__device__ __forceinline__ uint32_t packh(float a, float b) {
    __half2 t = __floats2half2_rn(a, b);
    return *reinterpret_cast<uint32_t*>(&t);
}
__device__ __forceinline__ void store_split(bf16* Ch, bf16* Cl, size_t idx,
                                            float a, float b) {
    bf16 ha = __float2bfloat16_rn(a), hb = __float2bfloat16_rn(b);
    bf162 hp; hp.x = ha; hp.y = hb;
    *reinterpret_cast<bf162*>(Ch + idx) = hp;
    bf162 lp = __floats2bfloat162_rn(a - __bfloat162float(ha),
                                     b - __bfloat162float(hb));
    *reinterpret_cast<bf162*>(Cl + idx) = lp;
}
__device__ __forceinline__ void cpasync16(void* dst, const void* src) {
    asm volatile("cp.async.cg.shared.global [%0], [%1], 16;"
                 :: "r"(saddr(dst)), "l"(src));
}
__device__ __forceinline__ void cp_commit() {
    asm volatile("cp.async.commit_group;" ::: "memory");
}
template <int N> __device__ __forceinline__ void cp_wait() {
    asm volatile("cp.async.wait_group %0;" :: "n"(N) : "memory");
}

// ---------------- h = x + pe, plus hi/lo split ----------------
__global__ __launch_bounds__(256) void add_pe_split(const float* __restrict__ x,
                                                    float* __restrict__ h,
                                                    bf16* __restrict__ hh,
                                                    bf16* __restrict__ hl) {
    int row = blockIdx.x;
    int c0  = threadIdx.x * 4;
    const float kf = -9.210340371976184f / (float)DIM;
    float4 xv = *reinterpret_cast<const float4*>(x + (size_t)row * DIM + c0);
    float v[4] = {xv.x, xv.y, xv.z, xv.w};
    float o[4];
#pragma unroll
    for (int e = 0; e < 4; e++) {
        int c = c0 + e;
        float div = expf((float)(c & ~1) * kf);
        float arg = (float)row * div;
        o[e] = v[e] + ((c & 1) ? cosf(arg) : sinf(arg));
    }
    size_t base = (size_t)row * DIM + c0;
    *reinterpret_cast<float4*>(h + base) = make_float4(o[0], o[1], o[2], o[3]);
    store_split(hh, hl, base + 0, o[0], o[1]);
    store_split(hh, hl, base + 2, o[2], o[3]);
}

// ---------------- weight split + transpose: Wt[n,k] = W[k,n] ----------------
__global__ __launch_bounds__(256) void wsplit_t(const float* __restrict__ W,
                                                bf16* __restrict__ hi,
                                                bf16* __restrict__ lo) {
    __shared__ float t[32][33];
    int k0 = blockIdx.x * 32, n0 = blockIdx.y * 32;
    int tx = threadIdx.x, ty = threadIdx.y;
#pragma unroll
    for (int j = 0; j < 4; j++)
        t[ty + 8 * j][tx] = W[(size_t)(k0 + ty + 8 * j) * DIM + n0 + tx];
    __syncthreads();
#pragma unroll
    for (int j = 0; j < 4; j++) {
        int n = n0 + ty + 8 * j, k = k0 + tx;
        float v = t[tx][ty + 8 * j];
        bf16 h = __float2bfloat16_rn(v);
        hi[(size_t)n * DIM + k] = h;
        lo[(size_t)n * DIM + k] = __float2bfloat16_rn(v - __bfloat162float(h));
    }
}

// ---------------- split-bf16 GEMM, cp.async 2-stage pipeline ----------------
// MODE 0: fp16 output (q/k/v); MODE 1: fp32 output (out-proj)
#define GKCH 32

template <int MODE>
__global__ __launch_bounds__(256, 2) void gemm_cp(
    const bf16* __restrict__ Ah, const bf16* __restrict__ Al,
    const bf16* __restrict__ Bh, const bf16* __restrict__ Bl,
    const float* __restrict__ bias,
    __half* __restrict__ Cx, float* __restrict__ Cf) {
    extern __shared__ bf16 sm[];
    const int tid  = threadIdx.x;
    const int warp = tid >> 5, lane = tid & 31;
    const int g = lane >> 2, t4 = lane & 3;
    const int lr = lane & 7, sub = lane >> 3;
    const int wm = warp & 3, wn = warp >> 2;
    const int m0 = blockIdx.y * 128, n0 = blockIdx.x * 128;

    auto load_chunk = [&](int kb, int st) {
        bf16* sA = sm + st * 16384;
        bf16* sB = sA + 8192;
#pragma unroll
        for (int i = 0; i < 4; i++) {
            int id = tid + i * 256;          // 0..1023
            int r = id >> 3, cc = id & 7;
            int sidx = (r * 8 + ((cc ^ r) & 7)) * 8;
            const bf16* sa = (cc < 4)
                ? Ah + (size_t)(m0 + r) * DIM + kb * GKCH + cc * 8
                : Al + (size_t)(m0 + r) * DIM + kb * GKCH + (cc - 4) * 8;
            cpasync16(sA + sidx, sa);
            const bf16* sb = (cc < 4)
                ? Bh + (size_t)(n0 + r) * DIM + kb * GKCH + cc * 8
                : Bl + (size_t)(n0 + r) * DIM + kb * GKCH + (cc - 4) * 8;
            cpasync16(sB + sidx, sb);
        }
    };

    float acc[2][8][4];
#pragma unroll
    for (int mt = 0; mt < 2; mt++)
#pragma unroll
        for (int nt = 0; nt < 8; nt++)
#pragma unroll
            for (int e = 0; e < 4; e++) acc[mt][nt][e] = 0.f;

    load_chunk(0, 0);
    cp_commit();

    const int NCH = DIM / GKCH;          // 32
    for (int kb = 0; kb < NCH; kb++) {
        int st = kb & 1;
        if (kb + 1 < NCH) { load_chunk(kb + 1, st ^ 1); cp_commit(); cp_wait<1>(); }
        else              { cp_wait<0>(); }
        __syncthreads();
        bf16* sA = sm + st * 16384;
        bf16* sB = sA + 8192;
#pragma unroll
        for (int kk = 0; kk < 2; kk++) {
            uint32_t ah[2][4], al[2][4];
#pragma unroll
            for (int mt = 0; mt < 2; mt++) {
                int ar = wm * 32 + mt * 16 + lr + (sub & 1) * 8;
                int ac = kk * 16 + (sub >> 1) * 8;
                ldsm4(ah[mt], saddr(sA + swzi64(ar, ac)));
                ldsm4(al[mt], saddr(sA + swzi64(ar, ac + 32)));
            }
#pragma unroll
            for (int ntt = 0; ntt < 4; ntt++) {
                int br = wn * 64 + ntt * 16 + lr + (sub >> 1) * 8;
                int bc = kk * 16 + (sub & 1) * 8;
                uint32_t bh[4], bl[4];
                ldsm4(bh, saddr(sB + swzi64(br, bc)));
                ldsm4(bl, saddr(sB + swzi64(br, bc + 32)));
#pragma unroll
                for (int mt = 0; mt < 2; mt++) {
                    mma_bf(acc[mt][2 * ntt], ah[mt], bh[0], bh[1]);
                    mma_bf(acc[mt][2 * ntt], al[mt], bh[0], bh[1]);
                    mma_bf(acc[mt][2 * ntt], ah[mt], bl[0], bl[1]);
                    mma_bf(acc[mt][2 * ntt + 1], ah[mt], bh[2], bh[3]);
                    mma_bf(acc[mt][2 * ntt + 1], al[mt], bh[2], bh[3]);
                    mma_bf(acc[mt][2 * ntt + 1], ah[mt], bl[2], bl[3]);
                }
            }
        }
        __syncthreads();
    }

#pragma unroll
    for (int mt = 0; mt < 2; mt++) {
#pragma unroll
        for (int nt = 0; nt < 8; nt++) {
            int row0 = m0 + wm * 32 + mt * 16 + g;
            int col  = n0 + wn * 64 + nt * 8 + t4 * 2;
            float b0 = bias[col], b1 = bias[col + 1];
            float v00 = acc[mt][nt][0] + b0, v01 = acc[mt][nt][1] + b1;
            float v10 = acc[mt][nt][2] + b0, v11 = acc[mt][nt][3] + b1;
            if (MODE == 0) {
                *reinterpret_cast<__half2*>(Cx + (size_t)row0 * DIM + col) =
                    __floats2half2_rn(v00, v01);
                *reinterpret_cast<__half2*>(Cx + (size_t)(row0 + 8) * DIM + col) =
                    __floats2half2_rn(v10, v11);
            } else {
                *reinterpret_cast<float2*>(Cf + (size_t)row0 * DIM + col) =
                    make_float2(v00, v01);
                *reinterpret_cast<float2*>(Cf + (size_t)(row0 + 8) * DIM + col) =
                    make_float2(v10, v11);
            }
        }
    }
}

// ---------------- flash attention: fp16 single-product, cp.async pipeline ----
// smem (halfs): Q[0..8191] | K st0 [8192..12287] | K st1 [12288..16383]
//               | V st0 [16384..20479] | V st1 [20480..24575]  = 49152 bytes
__global__ __launch_bounds__(256, 2) void flash_hf(
    const __half* __restrict__ Qf,
    const __half* __restrict__ Kf,
    const __half* __restrict__ Vf,
    bf16* __restrict__ Oh, bf16* __restrict__ Ol) {
    extern __shared__ __half smh[];
    __half* sQ = smh;                    // 128 x 64

    const int tid  = threadIdx.x;
    const int warp = tid >> 5, lane = tid & 31;
    const int g = lane >> 2, t4 = lane & 3;
    const int lr = lane & 7, sub = lane >> 3;
    const int rbase = warp * 16;
    const int head  = blockIdx.y;
    const int qt    = blockIdx.x;

    // Q via cp.async (group 0 includes Q + first KV stage)
    {
        const __half* qb = Qf + (size_t)(qt * 128) * DIM + head * DHEAD;
#pragma unroll
        for (int i = 0; i < 4; i++) {
            int id = tid + i * 256;
            int r = id >> 3, cc = id & 7;
            cpasync16(sQ + (r * 64 + ((cc ^ r) & 7) * 8),
                      qb + (size_t)r * DIM + cc * 8);
        }
    }
    auto load_kv = [&](int t, int st) {
        __half* sK = smh + 8192  + st * 4096;    // 64x64 tile = 4096 halfs
        __half* sV = smh + 16384 + st * 4096;
        const size_t base = (size_t)(t * 64) * DIM + head * DHEAD;
#pragma unroll
        for (int i = 0; i < 2; i++) {
            int id = tid + i * 256;          // 0..511 quad ids
            int r = id >> 3, cc = id & 7;
            int sidx = (r * 8 + ((cc ^ r) & 7)) * 8;
            cpasync16(sK + sidx, Kf + base + (size_t)r * DIM + cc * 8);
            cpasync16(sV + sidx, Vf + base + (size_t)r * DIM + cc * 8);
        }
    };

    float m_i[2], l_i[2], o[8][4];
    m_i[0] = m_i[1] = -1e30f;
    l_i[0] = l_i[1] = 0.f;
#pragma unroll
    for (int nt = 0; nt < 8; nt++)
#pragma unroll
        for (int e = 0; e < 4; e++) o[nt][e] = 0.f;

    const float scale = 0.18033688011112042f;   // (1/8)*log2(e)
    const int NT = SEQ / 64;

    load_kv(0, 0);
    cp_commit();

    for (int t = 0; t < NT; t++) {
        int st = t & 1;
        if (t + 1 < NT) { load_kv(t + 1, st ^ 1); cp_commit(); cp_wait<1>(); }
        else            { cp_wait<0>(); }
        __syncthreads();
        __half* sK = smh + 8192  + st * 4096;
        __half* sV = smh + 16384 + st * 4096;

        // ---- S = Q * K^T (single fp16 product) ----
        float s[8][4];
#pragma unroll
        for (int nt = 0; nt < 8; nt++)
#pragma unroll
            for (int e = 0; e < 4; e++) s[nt][e] = 0.f;
#pragma unroll
        for (int kk = 0; kk < 4; kk++) {
            uint32_t qf[4];
            ldsm4(qf, saddr(sQ + swzi64(rbase + lr + (sub & 1) * 8,
                                        kk * 16 + (sub >> 1) * 8)));
#pragma unroll
            for (int ntt = 0; ntt < 4; ntt++) {
                int krow = ntt * 16 + lr + (sub >> 1) * 8;
                int kcol = kk * 16 + (sub & 1) * 8;
                uint32_t kf[4];
                ldsm4(kf, saddr(sK + swzi64(krow, kcol)));
                mma_hf(s[2 * ntt],     qf, kf[0], kf[1]);
                mma_hf(s[2 * ntt + 1], qf, kf[2], kf[3]);
            }
        }

        // ---- online softmax (log2 domain) ----
#pragma unroll
        for (int r = 0; r < 2; r++) {
            float mx = -1e30f;
#pragma unroll
            for (int j = 0; j < 8; j++) {
                s[j][2 * r]     *= scale;
                s[j][2 * r + 1] *= scale;
                mx = fmaxf(mx, fmaxf(s[j][2 * r], s[j][2 * r + 1]));
            }
            mx = fmaxf(mx, __shfl_xor_sync(0xffffffffu, mx, 1));
            mx = fmaxf(mx, __shfl_xor_sync(0xffffffffu, mx, 2));
            float mnew = fmaxf(m_i[r], mx);
            float corr = ex2f(m_i[r] - mnew);
            m_i[r] = mnew;
            float rs = 0.f;
#pragma unroll
            for (int j = 0; j < 8; j++) {
                float p0 = ex2f(s[j][2 * r] - mnew);
                float p1 = ex2f(s[j][2 * r + 1] - mnew);
                s[j][2 * r] = p0; s[j][2 * r + 1] = p1;
                rs += p0 + p1;
            }
            rs += __shfl_xor_sync(0xffffffffu, rs, 1);
            rs += __shfl_xor_sync(0xffffffffu, rs, 2);
            l_i[r] = l_i[r] * corr + rs;
#pragma unroll
            for (int nt = 0; nt < 8; nt++) {
                o[nt][2 * r]     *= corr;
                o[nt][2 * r + 1] *= corr;
            }
        }

        // ---- O += P * V (single fp16 product) ----
#pragma unroll
        for (int kk = 0; kk < 4; kk++) {
            int j0 = 2 * kk, j1 = j0 + 1;
            uint32_t aH[4];
            aH[0] = packh(s[j0][0], s[j0][1]);
            aH[1] = packh(s[j0][2], s[j0][3]);
            aH[2] = packh(s[j1][0], s[j1][1]);
            aH[3] = packh(s[j1][2], s[j1][3]);
#pragma unroll
            for (int ntt = 0; ntt < 4; ntt++) {
                int vrow = kk * 16 + lr + (sub & 1) * 8;
                int vcol = ntt * 16 + (sub >> 1) * 8;
                uint32_t vf[4];
                ldsm4t(vf, saddr(sV + swzi64(vrow, vcol)));
                mma_hf(o[2 * ntt],     aH, vf[0], vf[1]);
                mma_hf(o[2 * ntt + 1], aH, vf[2], vf[3]);
            }
        }
        __syncthreads();
    }

    float inv0 = 1.f / l_i[0], inv1 = 1.f / l_i[1];
#pragma unroll
    for (int nt = 0; nt < 8; nt++) {
        int row0 = qt * 128 + rbase + g;
        int col  = head * DHEAD + nt * 8 + t4 * 2;
        store_split(Oh, Ol, (size_t)row0 * DIM + col,
                    o[nt][0] * inv0, o[nt][1] * inv0);
        store_split(Oh, Ol, (size_t)(row0 + 8) * DIM + col,
                    o[nt][2] * inv1, o[nt][3] * inv1);
    }
}

// ---------------- residual + layernorm ----------------
__global__ __launch_bounds__(256) void ln_kernel(const float* __restrict__ h,
                                                 const float* __restrict__ pr,
                                                 const float* __restrict__ gamma,
                                                 const float* __restrict__ beta,
                                                 float* __restrict__ out) {
    __shared__ float red[16];
    __shared__ float s_mu, s_rstd;
    int row = blockIdx.x, tid = threadIdx.x;
    int c0 = tid * 4;
    float4 hv = *reinterpret_cast<const float4*>(h  + (size_t)row * DIM + c0);
    float4 pv = *reinterpret_cast<const float4*>(pr + (size_t)row * DIM + c0);
    float y[4] = {hv.x + pv.x, hv.y + pv.y, hv.z + pv.z, hv.w + pv.w};
    float sum = y[0] + y[1] + y[2] + y[3];
    float sq  = y[0]*y[0] + y[1]*y[1] + y[2]*y[2] + y[3]*y[3];
#pragma unroll
    for (int off = 16; off; off >>= 1) {
        sum += __shfl_xor_sync(0xffffffffu, sum, off);
        sq  += __shfl_xor_sync(0xffffffffu, sq,  off);
    }
    int w = tid >> 5;
    if ((tid & 31) == 0) { red[w] = sum; red[8 + w] = sq; }
    __syncthreads();
    if (tid == 0) {
        float ts = 0.f, tq = 0.f;
        for (int i = 0; i < 8; i++) { ts += red[i]; tq += red[8 + i]; }
        float mu = ts / (float)DIM;
        s_mu   = mu;
        s_rstd = rsqrtf(tq / (float)DIM - mu * mu + 1e-5f);
    }
    __syncthreads();
    float4 gv = *reinterpret_cast<const float4*>(gamma + c0);
    float4 bv = *reinterpret_cast<const float4*>(beta  + c0);
    float mu = s_mu, rs = s_rstd;
    float4 ov;
    ov.x = (y[0] - mu) * rs * gv.x + bv.x;
    ov.y = (y[1] - mu) * rs * gv.y + bv.y;
    ov.z = (y[2] - mu) * rs * gv.z + bv.z;
    ov.w = (y[3] - mu) * rs * gv.w + bv.w;
    *reinterpret_cast<float4*>(out + (size_t)row * DIM + c0) = ov;
}

// ---------------------------------------------------------------------------
extern "C" void kernel_launch(void* const* d_in, const int* in_sizes, int n_in,
                              void* d_out, int out_size) {
    (void)in_sizes; (void)n_in; (void)out_size;
    const float* x     = (const float*)d_in[0];
    const float* W[4]  = {(const float*)d_in[1], (const float*)d_in[3],
                          (const float*)d_in[5], (const float*)d_in[7]};
    const float* bq    = (const float*)d_in[2];
    const float* bk    = (const float*)d_in[4];
    const float* bv    = (const float*)d_in[6];
    const float* bo    = (const float*)d_in[8];
    const float* gamma = (const float*)d_in[9];
    const float* beta  = (const float*)d_in[10];
    float* out = (float*)d_out;

    void* p;
    cudaGetSymbolAddress(&p, g_h);    float* h    = (float*)p;
    cudaGetSymbolAddress(&p, g_proj); float* proj = (float*)p;
    cudaGetSymbolAddress(&p, g_hh);   bf16* hh = (bf16*)p;
    cudaGetSymbolAddress(&p, g_hl);   bf16* hl = (bf16*)p;
    cudaGetSymbolAddress(&p, g_wh);   bf16* wh = (bf16*)p;
    cudaGetSymbolAddress(&p, g_wl);   bf16* wl = (bf16*)p;
    cudaGetSymbolAddress(&p, g_qf);   __half* qf = (__half*)p;
    cudaGetSymbolAddress(&p, g_kf);   __half* kf = (__half*)p;
    cudaGetSymbolAddress(&p, g_vf);   __half* vf = (__half*)p;
    cudaGetSymbolAddress(&p, g_aoh);  bf16* aoh = (bf16*)p;
    cudaGetSymbolAddress(&p, g_aol);  bf16* aol = (bf16*)p;

    const int SMEM_G = 65536;            // 2 stages x 32KB
    const int SMEM_F = 49152;            // Q 16KB + (K+V) x 2 stages x 8KB
    cudaFuncSetAttribute(gemm_cp<0>,
                         cudaFuncAttributeMaxDynamicSharedMemorySize, SMEM_G);
    cudaFuncSetAttribute(gemm_cp<1>,
                         cudaFuncAttributeMaxDynamicSharedMemorySize, SMEM_G);
    cudaFuncSetAttribute(flash_hf,
                         cudaFuncAttributeMaxDynamicSharedMemorySize, SMEM_F);

    add_pe_split<<<SEQ, 256>>>(x, h, hh, hl);
    dim3 tg(DIM / 32, DIM / 32);
    for (int i = 0; i < 4; i++)
        wsplit_t<<<tg, dim3(32, 8)>>>(W[i], wh + (size_t)i * DIM * DIM,
                                      wl + (size_t)i * DIM * DIM);

    dim3 gg(DIM / 128, SEQ / 128);
    gemm_cp<0><<<gg, 256, SMEM_G>>>(hh, hl, wh + 0 * (size_t)DIM * DIM,
                                    wl + 0 * (size_t)DIM * DIM, bq, qf, nullptr);
    gemm_cp<0><<<gg, 256, SMEM_G>>>(hh, hl, wh + 1 * (size_t)DIM * DIM,
                                    wl + 1 * (size_t)DIM * DIM, bk, kf, nullptr);
    gemm_cp<0><<<gg, 256, SMEM_G>>>(hh, hl, wh + 2 * (size_t)DIM * DIM,
                                    wl + 2 * (size_t)DIM * DIM, bv, vf, nullptr);

    flash_hf<<<dim3(SEQ / 128, NHEAD), 256, SMEM_F>>>(qf, kf, vf, aoh, aol);

    gemm_cp<1><<<gg, 256, SMEM_G>>>(aoh, aol, wh + 3 * (size_t)DIM * DIM,
                                    wl + 3 * (size_t)DIM * DIM, bo,
                                    nullptr, proj);

    ln_kernel<<<SEQ, 256>>>(h, proj, gamma, beta, out);
}

// round 7
// speedup vs baseline: 6.9110x; 1.3548x over previous
#include <cuda_runtime.h>
#include <cuda_bf16.h>
#include <cuda_fp16.h>
#include <math.h>
#include <stdint.h>

#define SEQ   4096
#define DIM   1024
#define NHEAD 16
#define DHEAD 64

typedef __nv_bfloat16 bf16;
typedef __nv_bfloat162 bf162;

// ---------------- scratch (no cudaMalloc allowed) ----------------
__device__ float  g_h   [SEQ*DIM];     // x + pe (fp32, residual)
__device__ float  g_proj[SEQ*DIM];     // final projection out (fp32)
__device__ __half g_hf[SEQ*DIM];       // x + pe (fp16, qkv GEMM input)
__device__ __half g_wf[3][DIM*DIM];    // Wq/Wk/Wv fp16, TRANSPOSED [N,K]
__device__ bf16   g_woh[DIM*DIM], g_wol[DIM*DIM];  // Wo bf16 hi/lo, [N,K]
__device__ __half g_qf[SEQ*DIM], g_kf[SEQ*DIM], g_vf[SEQ*DIM];
__device__ bf16   g_aoh[SEQ*DIM], g_aol[SEQ*DIM];

// ---------------- helpers ----------------
__device__ __forceinline__ uint32_t saddr(const void* p) {
    return (uint32_t)__cvta_generic_to_shared(p);
}
__device__ __forceinline__ float ex2f(float x) {
    float y; asm("ex2.approx.f32 %0, %1;" : "=f"(y) : "f"(x)); return y;
}
__device__ __forceinline__ int swzi64(int row, int col) {
    return row * 64 + ((((col >> 3) ^ row) & 7) << 3);
}
__device__ __forceinline__ void ldsm4(uint32_t* r, uint32_t a) {
    asm volatile("ldmatrix.sync.aligned.m8n8.x4.shared.b16 {%0,%1,%2,%3},[%4];"
                 : "=r"(r[0]), "=r"(r[1]), "=r"(r[2]), "=r"(r[3]) : "r"(a));
}
__device__ __forceinline__ void ldsm4t(uint32_t* r, uint32_t a) {
    asm volatile("ldmatrix.sync.aligned.m8n8.x4.trans.shared.b16 {%0,%1,%2,%3},[%4];"
                 : "=r"(r[0]), "=r"(r[1]), "=r"(r[2]), "=r"(r[3]) : "r"(a));
}
__device__ __forceinline__ void mma_bf(float* c, const uint32_t* a,
                                       uint32_t b0, uint32_t b1) {
    asm volatile(
        "mma.sync.aligned.m16n8k16.row.col.f32.bf16.bf16.f32 "
        "{%0,%1,%2,%3},{%4,%5,%6,%7},{%8,%9},{%0,%1,%2,%3};"
        : "+f"(c[0]), "+f"(c[1]), "+f"(c[2]), "+f"(c[3])
        : "r"(a[0]), "r"(a[1]), "r"(a[2]), "r"(a[3]), "r"(b0), "r"(b1));
}
__device__ __forceinline__ void mma_hf(float* c, const uint32_t* a,
                                       uint32_t b0, uint32_t b1) {
    asm volatile(
        "mma.sync.aligned.m16n8k16.row.col.f32.f16.f16.f32 "
        "{%0,%1,%2,%3},{%4,%5,%6,%7},{%8,%9},{%0,%1,%2,%3};"
        : "+f"(c[0]), "+f"(c[1]), "+f"(c[2]), "+f"(c[3])
        : "r"(a[0]), "r"(a[1]), "r"(a[2]), "r"(a[3]), "r"(b0), "r"(b1));
}
__device__ __forceinline__ uint32_t packh(float a, float b) {
    __half2 t = __floats2half2_rn(a, b);
    return *reinterpret_cast<uint32_t*>(&t);
}
__device__ __forceinline__ void store_split(bf16* Ch, bf16* Cl, size_t idx,
                                            float a, float b) {
    bf16 ha = __float2bfloat16_rn(a), hb = __float2bfloat16_rn(b);
    bf162 hp; hp.x = ha; hp.y = hb;
    *reinterpret_cast<bf162*>(Ch + idx) = hp;
    bf162 lp = __floats2bfloat162_rn(a - __bfloat162float(ha),
                                     b - __bfloat162float(hb));
    *reinterpret_cast<bf162*>(Cl + idx) = lp;
}
__device__ __forceinline__ void cpasync16(void* dst, const void* src) {
    asm volatile("cp.async.cg.shared.global [%0], [%1], 16;"
                 :: "r"(saddr(dst)), "l"(src));
}
__device__ __forceinline__ void cp_commit() {
    asm volatile("cp.async.commit_group;" ::: "memory");
}
template <int N> __device__ __forceinline__ void cp_wait() {
    asm volatile("cp.async.wait_group %0;" :: "n"(N) : "memory");
}

// ---------------- h = x + pe (fp32 + fp16) ----------------
__global__ __launch_bounds__(256) void add_pe(const float* __restrict__ x,
                                              float* __restrict__ h,
                                              __half* __restrict__ hf) {
    int row = blockIdx.x;
    int c0  = threadIdx.x * 4;
    const float kf = -9.210340371976184f / (float)DIM;
    float4 xv = *reinterpret_cast<const float4*>(x + (size_t)row * DIM + c0);
    float v[4] = {xv.x, xv.y, xv.z, xv.w};
    float o[4];
#pragma unroll
    for (int e = 0; e < 4; e++) {
        int c = c0 + e;
        float div = expf((float)(c & ~1) * kf);
        float arg = (float)row * div;
        o[e] = v[e] + ((c & 1) ? cosf(arg) : sinf(arg));
    }
    size_t base = (size_t)row * DIM + c0;
    *reinterpret_cast<float4*>(h + base) = make_float4(o[0], o[1], o[2], o[3]);
    *reinterpret_cast<__half2*>(hf + base)     = __floats2half2_rn(o[0], o[1]);
    *reinterpret_cast<__half2*>(hf + base + 2) = __floats2half2_rn(o[2], o[3]);
}

// ---------------- fp16 weight transpose (3 weights): Wt[n,k] = W[k,n] --------
__global__ __launch_bounds__(256) void whalf_t(const float* __restrict__ W0,
                                               const float* __restrict__ W1,
                                               const float* __restrict__ W2,
                                               __half* __restrict__ outw) {
    __shared__ float t[32][33];
    const float* W = (blockIdx.z == 0) ? W0 : ((blockIdx.z == 1) ? W1 : W2);
    __half* o = outw + (size_t)blockIdx.z * DIM * DIM;
    int k0 = blockIdx.x * 32, n0 = blockIdx.y * 32;
    int tx = threadIdx.x, ty = threadIdx.y;
#pragma unroll
    for (int j = 0; j < 4; j++)
        t[ty + 8 * j][tx] = W[(size_t)(k0 + ty + 8 * j) * DIM + n0 + tx];
    __syncthreads();
#pragma unroll
    for (int j = 0; j < 4; j++)
        o[(size_t)(n0 + ty + 8 * j) * DIM + k0 + tx] =
            __float2half_rn(t[tx][ty + 8 * j]);
}

// ---------------- Wo split+transpose (bf16 hi/lo) ----------------
__global__ __launch_bounds__(256) void wsplit_t(const float* __restrict__ W,
                                                bf16* __restrict__ hi,
                                                bf16* __restrict__ lo) {
    __shared__ float t[32][33];
    int k0 = blockIdx.x * 32, n0 = blockIdx.y * 32;
    int tx = threadIdx.x, ty = threadIdx.y;
#pragma unroll
    for (int j = 0; j < 4; j++)
        t[ty + 8 * j][tx] = W[(size_t)(k0 + ty + 8 * j) * DIM + n0 + tx];
    __syncthreads();
#pragma unroll
    for (int j = 0; j < 4; j++) {
        int n = n0 + ty + 8 * j, k = k0 + tx;
        float v = t[tx][ty + 8 * j];
        bf16 h = __float2bfloat16_rn(v);
        hi[(size_t)n * DIM + k] = h;
        lo[(size_t)n * DIM + k] = __float2bfloat16_rn(v - __bfloat162float(h));
    }
}

// ---------------- fused q/k/v GEMM: single fp16 product ----------------
// grid (24, 32): blockIdx.x>>3 selects {q,k,v}; K-chunk 64; 2 stages x 32KB.
__global__ __launch_bounds__(256, 2) void gemm_qkv(
    const __half* __restrict__ A, const __half* __restrict__ Wf,
    const float* __restrict__ bq, const float* __restrict__ bk,
    const float* __restrict__ bv,
    __half* __restrict__ Qo, __half* __restrict__ Ko, __half* __restrict__ Vo) {
    extern __shared__ __half smq[];
    const int tid  = threadIdx.x;
    const int warp = tid >> 5, lane = tid & 31;
    const int g = lane >> 2, t4 = lane & 3;
    const int lr = lane & 7, sub = lane >> 3;
    const int wm = warp & 3, wn = warp >> 2;
    const int wsel = blockIdx.x >> 3;
    const int n0 = (blockIdx.x & 7) * 128;
    const int m0 = blockIdx.y * 128;
    const __half* B = Wf + (size_t)wsel * DIM * DIM;
    const float* bias = (wsel == 0) ? bq : ((wsel == 1) ? bk : bv);
    __half* C = (wsel == 0) ? Qo : ((wsel == 1) ? Ko : Vo);

    auto load_chunk = [&](int kb, int st) {
        __half* sA = smq + st * 16384;
        __half* sB = sA + 8192;
#pragma unroll
        for (int i = 0; i < 4; i++) {
            int id = tid + i * 256;          // 0..1023
            int r = id >> 3, cc = id & 7;
            int sidx = (r * 8 + ((cc ^ r) & 7)) * 8;
            cpasync16(sA + sidx, A + (size_t)(m0 + r) * DIM + kb * 64 + cc * 8);
            cpasync16(sB + sidx, B + (size_t)(n0 + r) * DIM + kb * 64 + cc * 8);
        }
    };

    float acc[2][8][4];
#pragma unroll
    for (int mt = 0; mt < 2; mt++)
#pragma unroll
        for (int nt = 0; nt < 8; nt++)
#pragma unroll
            for (int e = 0; e < 4; e++) acc[mt][nt][e] = 0.f;

    load_chunk(0, 0);
    cp_commit();

    const int NCH = DIM / 64;            // 16
    for (int kb = 0; kb < NCH; kb++) {
        int st = kb & 1;
        if (kb + 1 < NCH) { load_chunk(kb + 1, st ^ 1); cp_commit(); cp_wait<1>(); }
        else              { cp_wait<0>(); }
        __syncthreads();
        __half* sA = smq + st * 16384;
        __half* sB = sA + 8192;
#pragma unroll
        for (int kk = 0; kk < 4; kk++) {
            uint32_t af[2][4];
#pragma unroll
            for (int mt = 0; mt < 2; mt++)
                ldsm4(af[mt], saddr(sA + swzi64(wm * 32 + mt * 16 + lr + (sub & 1) * 8,
                                                kk * 16 + (sub >> 1) * 8)));
#pragma unroll
            for (int ntt = 0; ntt < 4; ntt++) {
                uint32_t bfg[4];
                ldsm4(bfg, saddr(sB + swzi64(wn * 64 + ntt * 16 + lr + (sub >> 1) * 8,
                                             kk * 16 + (sub & 1) * 8)));
#pragma unroll
                for (int mt = 0; mt < 2; mt++) {
                    mma_hf(acc[mt][2 * ntt],     af[mt], bfg[0], bfg[1]);
                    mma_hf(acc[mt][2 * ntt + 1], af[mt], bfg[2], bfg[3]);
                }
            }
        }
        __syncthreads();
    }

#pragma unroll
    for (int mt = 0; mt < 2; mt++) {
#pragma unroll
        for (int nt = 0; nt < 8; nt++) {
            int row0 = m0 + wm * 32 + mt * 16 + g;
            int col  = n0 + wn * 64 + nt * 8 + t4 * 2;
            float b0 = bias[col], b1 = bias[col + 1];
            *reinterpret_cast<__half2*>(C + (size_t)row0 * DIM + col) =
                __floats2half2_rn(acc[mt][nt][0] + b0, acc[mt][nt][1] + b1);
            *reinterpret_cast<__half2*>(C + (size_t)(row0 + 8) * DIM + col) =
                __floats2half2_rn(acc[mt][nt][2] + b0, acc[mt][nt][3] + b1);
        }
    }
}

// ---------------- out-proj GEMM: split-bf16 3-product, fp32 out ----------------
#define GKCH 32
__global__ __launch_bounds__(256, 2) void gemm_out(
    const bf16* __restrict__ Ah, const bf16* __restrict__ Al,
    const bf16* __restrict__ Bh, const bf16* __restrict__ Bl,
    const float* __restrict__ bias, float* __restrict__ Cf) {
    extern __shared__ bf16 sm[];
    const int tid  = threadIdx.x;
    const int warp = tid >> 5, lane = tid & 31;
    const int g = lane >> 2, t4 = lane & 3;
    const int lr = lane & 7, sub = lane >> 3;
    const int wm = warp & 3, wn = warp >> 2;
    const int m0 = blockIdx.y * 128, n0 = blockIdx.x * 128;

    auto load_chunk = [&](int kb, int st) {
        bf16* sA = sm + st * 16384;
        bf16* sB = sA + 8192;
#pragma unroll
        for (int i = 0; i < 4; i++) {
            int id = tid + i * 256;
            int r = id >> 3, cc = id & 7;
            int sidx = (r * 8 + ((cc ^ r) & 7)) * 8;
            const bf16* sa = (cc < 4)
                ? Ah + (size_t)(m0 + r) * DIM + kb * GKCH + cc * 8
                : Al + (size_t)(m0 + r) * DIM + kb * GKCH + (cc - 4) * 8;
            cpasync16(sA + sidx, sa);
            const bf16* sb = (cc < 4)
                ? Bh + (size_t)(n0 + r) * DIM + kb * GKCH + cc * 8
                : Bl + (size_t)(n0 + r) * DIM + kb * GKCH + (cc - 4) * 8;
            cpasync16(sB + sidx, sb);
        }
    };

    float acc[2][8][4];
#pragma unroll
    for (int mt = 0; mt < 2; mt++)
#pragma unroll
        for (int nt = 0; nt < 8; nt++)
#pragma unroll
            for (int e = 0; e < 4; e++) acc[mt][nt][e] = 0.f;

    load_chunk(0, 0);
    cp_commit();

    const int NCH = DIM / GKCH;
    for (int kb = 0; kb < NCH; kb++) {
        int st = kb & 1;
        if (kb + 1 < NCH) { load_chunk(kb + 1, st ^ 1); cp_commit(); cp_wait<1>(); }
        else              { cp_wait<0>(); }
        __syncthreads();
        bf16* sA = sm + st * 16384;
        bf16* sB = sA + 8192;
#pragma unroll
        for (int kk = 0; kk < 2; kk++) {
            uint32_t ah[2][4], al[2][4];
#pragma unroll
            for (int mt = 0; mt < 2; mt++) {
                int ar = wm * 32 + mt * 16 + lr + (sub & 1) * 8;
                int ac = kk * 16 + (sub >> 1) * 8;
                ldsm4(ah[mt], saddr(sA + swzi64(ar, ac)));
                ldsm4(al[mt], saddr(sA + swzi64(ar, ac + 32)));
            }
#pragma unroll
            for (int ntt = 0; ntt < 4; ntt++) {
                int br = wn * 64 + ntt * 16 + lr + (sub >> 1) * 8;
                int bc = kk * 16 + (sub & 1) * 8;
                uint32_t bh[4], bl[4];
                ldsm4(bh, saddr(sB + swzi64(br, bc)));
                ldsm4(bl, saddr(sB + swzi64(br, bc + 32)));
#pragma unroll
                for (int mt = 0; mt < 2; mt++) {
                    mma_bf(acc[mt][2 * ntt], ah[mt], bh[0], bh[1]);
                    mma_bf(acc[mt][2 * ntt], al[mt], bh[0], bh[1]);
                    mma_bf(acc[mt][2 * ntt], ah[mt], bl[0], bl[1]);
                    mma_bf(acc[mt][2 * ntt + 1], ah[mt], bh[2], bh[3]);
                    mma_bf(acc[mt][2 * ntt + 1], al[mt], bh[2], bh[3]);
                    mma_bf(acc[mt][2 * ntt + 1], ah[mt], bl[2], bl[3]);
                }
            }
        }
        __syncthreads();
    }

#pragma unroll
    for (int mt = 0; mt < 2; mt++) {
#pragma unroll
        for (int nt = 0; nt < 8; nt++) {
            int row0 = m0 + wm * 32 + mt * 16 + g;
            int col  = n0 + wn * 64 + nt * 8 + t4 * 2;
            float b0 = bias[col], b1 = bias[col + 1];
            *reinterpret_cast<float2*>(Cf + (size_t)row0 * DIM + col) =
                make_float2(acc[mt][nt][0] + b0, acc[mt][nt][1] + b1);
            *reinterpret_cast<float2*>(Cf + (size_t)(row0 + 8) * DIM + col) =
                make_float2(acc[mt][nt][2] + b0, acc[mt][nt][3] + b1);
        }
    }
}

// ---------------- flash attention: fp16 single-product, cp.async pipeline ----
__global__ __launch_bounds__(256, 2) void flash_hf(
    const __half* __restrict__ Qf,
    const __half* __restrict__ Kf,
    const __half* __restrict__ Vf,
    bf16* __restrict__ Oh, bf16* __restrict__ Ol) {
    extern __shared__ __half smh[];
    __half* sQ = smh;                    // 128 x 64

    const int tid  = threadIdx.x;
    const int warp = tid >> 5, lane = tid & 31;
    const int g = lane >> 2, t4 = lane & 3;
    const int lr = lane & 7, sub = lane >> 3;
    const int rbase = warp * 16;
    const int head  = blockIdx.y;
    const int qt    = blockIdx.x;

    {
        const __half* qb = Qf + (size_t)(qt * 128) * DIM + head * DHEAD;
#pragma unroll
        for (int i = 0; i < 4; i++) {
            int id = tid + i * 256;
            int r = id >> 3, cc = id & 7;
            cpasync16(sQ + (r * 64 + ((cc ^ r) & 7) * 8),
                      qb + (size_t)r * DIM + cc * 8);
        }
    }
    auto load_kv = [&](int t, int st) {
        __half* sK = smh + 8192  + st * 4096;
        __half* sV = smh + 16384 + st * 4096;
        const size_t base = (size_t)(t * 64) * DIM + head * DHEAD;
#pragma unroll
        for (int i = 0; i < 2; i++) {
            int id = tid + i * 256;
            int r = id >> 3, cc = id & 7;
            int sidx = (r * 8 + ((cc ^ r) & 7)) * 8;
            cpasync16(sK + sidx, Kf + base + (size_t)r * DIM + cc * 8);
            cpasync16(sV + sidx, Vf + base + (size_t)r * DIM + cc * 8);
        }
    };

    float m_i[2], l_i[2], o[8][4];
    m_i[0] = m_i[1] = -1e30f;
    l_i[0] = l_i[1] = 0.f;
#pragma unroll
    for (int nt = 0; nt < 8; nt++)
#pragma unroll
        for (int e = 0; e < 4; e++) o[nt][e] = 0.f;

    const float scale = 0.18033688011112042f;
    const int NT = SEQ / 64;

    load_kv(0, 0);
    cp_commit();

    for (int t = 0; t < NT; t++) {
        int st = t & 1;
        if (t + 1 < NT) { load_kv(t + 1, st ^ 1); cp_commit(); cp_wait<1>(); }
        else            { cp_wait<0>(); }
        __syncthreads();
        __half* sK = smh + 8192  + st * 4096;
        __half* sV = smh + 16384 + st * 4096;

        float s[8][4];
#pragma unroll
        for (int nt = 0; nt < 8; nt++)
#pragma unroll
            for (int e = 0; e < 4; e++) s[nt][e] = 0.f;
#pragma unroll
        for (int kk = 0; kk < 4; kk++) {
            uint32_t qf[4];
            ldsm4(qf, saddr(sQ + swzi64(rbase + lr + (sub & 1) * 8,
                                        kk * 16 + (sub >> 1) * 8)));
#pragma unroll
            for (int ntt = 0; ntt < 4; ntt++) {
                uint32_t kf[4];
                ldsm4(kf, saddr(sK + swzi64(ntt * 16 + lr + (sub >> 1) * 8,
                                            kk * 16 + (sub & 1) * 8)));
                mma_hf(s[2 * ntt],     qf, kf[0], kf[1]);
                mma_hf(s[2 * ntt + 1], qf, kf[2], kf[3]);
            }
        }

#pragma unroll
        for (int r = 0; r < 2; r++) {
            float mx = -1e30f;
#pragma unroll
            for (int j = 0; j < 8; j++) {
                s[j][2 * r]     *= scale;
                s[j][2 * r + 1] *= scale;
                mx = fmaxf(mx, fmaxf(s[j][2 * r], s[j][2 * r + 1]));
            }
            mx = fmaxf(mx, __shfl_xor_sync(0xffffffffu, mx, 1));
            mx = fmaxf(mx, __shfl_xor_sync(0xffffffffu, mx, 2));
            float mnew = fmaxf(m_i[r], mx);
            float corr = ex2f(m_i[r] - mnew);
            m_i[r] = mnew;
            float rs = 0.f;
#pragma unroll
            for (int j = 0; j < 8; j++) {
                float p0 = ex2f(s[j][2 * r] - mnew);
                float p1 = ex2f(s[j][2 * r + 1] - mnew);
                s[j][2 * r] = p0; s[j][2 * r + 1] = p1;
                rs += p0 + p1;
            }
            rs += __shfl_xor_sync(0xffffffffu, rs, 1);
            rs += __shfl_xor_sync(0xffffffffu, rs, 2);
            l_i[r] = l_i[r] * corr + rs;
#pragma unroll
            for (int nt = 0; nt < 8; nt++) {
                o[nt][2 * r]     *= corr;
                o[nt][2 * r + 1] *= corr;
            }
        }

#pragma unroll
        for (int kk = 0; kk < 4; kk++) {
            int j0 = 2 * kk, j1 = j0 + 1;
            uint32_t aH[4];
            aH[0] = packh(s[j0][0], s[j0][1]);
            aH[1] = packh(s[j0][2], s[j0][3]);
            aH[2] = packh(s[j1][0], s[j1][1]);
            aH[3] = packh(s[j1][2], s[j1][3]);
#pragma unroll
            for (int ntt = 0; ntt < 4; ntt++) {
                uint32_t vf[4];
                ldsm4t(vf, saddr(sV + swzi64(kk * 16 + lr + (sub & 1) * 8,
                                             ntt * 16 + (sub >> 1) * 8)));
                mma_hf(o[2 * ntt],     aH, vf[0], vf[1]);
                mma_hf(o[2 * ntt + 1], aH, vf[2], vf[3]);
            }
        }
        __syncthreads();
    }

    float inv0 = 1.f / l_i[0], inv1 = 1.f / l_i[1];
#pragma unroll
    for (int nt = 0; nt < 8; nt++) {
        int row0 = qt * 128 + rbase + g;
        int col  = head * DHEAD + nt * 8 + t4 * 2;
        store_split(Oh, Ol, (size_t)row0 * DIM + col,
                    o[nt][0] * inv0, o[nt][1] * inv0);
        store_split(Oh, Ol, (size_t)(row0 + 8) * DIM + col,
                    o[nt][2] * inv1, o[nt][3] * inv1);
    }
}

// ---------------- residual + layernorm ----------------
__global__ __launch_bounds__(256) void ln_kernel(const float* __restrict__ h,
                                                 const float* __restrict__ pr,
                                                 const float* __restrict__ gamma,
                                                 const float* __restrict__ beta,
                                                 float* __restrict__ out) {
    __shared__ float red[16];
    __shared__ float s_mu, s_rstd;
    int row = blockIdx.x, tid = threadIdx.x;
    int c0 = tid * 4;
    float4 hv = *reinterpret_cast<const float4*>(h  + (size_t)row * DIM + c0);
    float4 pv = *reinterpret_cast<const float4*>(pr + (size_t)row * DIM + c0);
    float y[4] = {hv.x + pv.x, hv.y + pv.y, hv.z + pv.z, hv.w + pv.w};
    float sum = y[0] + y[1] + y[2] + y[3];
    float sq  = y[0]*y[0] + y[1]*y[1] + y[2]*y[2] + y[3]*y[3];
#pragma unroll
    for (int off = 16; off; off >>= 1) {
        sum += __shfl_xor_sync(0xffffffffu, sum, off);
        sq  += __shfl_xor_sync(0xffffffffu, sq,  off);
    }
    int w = tid >> 5;
    if ((tid & 31) == 0) { red[w] = sum; red[8 + w] = sq; }
    __syncthreads();
    if (tid == 0) {
        float ts = 0.f, tq = 0.f;
        for (int i = 0; i < 8; i++) { ts += red[i]; tq += red[8 + i]; }
        float mu = ts / (float)DIM;
        s_mu   = mu;
        s_rstd = rsqrtf(tq / (float)DIM - mu * mu + 1e-5f);
    }
    __syncthreads();
    float4 gv = *reinterpret_cast<const float4*>(gamma + c0);
    float4 bv = *reinterpret_cast<const float4*>(beta  + c0);
    float mu = s_mu, rs = s_rstd;
    float4 ov;
    ov.x = (y[0] - mu) * rs * gv.x + bv.x;
    ov.y = (y[1] - mu) * rs * gv.y + bv.y;
    ov.z = (y[2] - mu) * rs * gv.z + bv.z;
    ov.w = (y[3] - mu) * rs * gv.w + bv.w;
    *reinterpret_cast<float4*>(out + (size_t)row * DIM + c0) = ov;
}

// ---------------------------------------------------------------------------
extern "C" void kernel_launch(void* const* d_in, const int* in_sizes, int n_in,
                              void* d_out, int out_size) {
    (void)in_sizes; (void)n_in; (void)out_size;
    const float* x     = (const float*)d_in[0];
    const float* Wq    = (const float*)d_in[1];
    const float* bq    = (const float*)d_in[2];
    const float* Wk    = (const float*)d_in[3];
    const float* bk    = (const float*)d_in[4];
    const float* Wv    = (const float*)d_in[5];
    const float* bv    = (const float*)d_in[6];
    const float* Wo    = (const float*)d_in[7];
    const float* bo    = (const float*)d_in[8];
    const float* gamma = (const float*)d_in[9];
    const float* beta  = (const float*)d_in[10];
    float* out = (float*)d_out;

    void* p;
    cudaGetSymbolAddress(&p, g_h);    float* h    = (float*)p;
    cudaGetSymbolAddress(&p, g_proj); float* proj = (float*)p;
    cudaGetSymbolAddress(&p, g_hf);   __half* hf = (__half*)p;
    cudaGetSymbolAddress(&p, g_wf);   __half* wf = (__half*)p;
    cudaGetSymbolAddress(&p, g_woh);  bf16* woh = (bf16*)p;
    cudaGetSymbolAddress(&p, g_wol);  bf16* wol = (bf16*)p;
    cudaGetSymbolAddress(&p, g_qf);   __half* qf = (__half*)p;
    cudaGetSymbolAddress(&p, g_kf);   __half* kf = (__half*)p;
    cudaGetSymbolAddress(&p, g_vf);   __half* vf = (__half*)p;
    cudaGetSymbolAddress(&p, g_aoh);  bf16* aoh = (bf16*)p;
    cudaGetSymbolAddress(&p, g_aol);  bf16* aol = (bf16*)p;

    const int SMEM_G = 65536;            // both GEMMs: 2 stages x 32KB
    const int SMEM_F = 49152;
    cudaFuncSetAttribute(gemm_qkv,
                         cudaFuncAttributeMaxDynamicSharedMemorySize, SMEM_G);
    cudaFuncSetAttribute(gemm_out,
                         cudaFuncAttributeMaxDynamicSharedMemorySize, SMEM_G);
    cudaFuncSetAttribute(flash_hf,
                         cudaFuncAttributeMaxDynamicSharedMemorySize, SMEM_F);

    add_pe<<<SEQ, 256>>>(x, h, hf);
    whalf_t<<<dim3(DIM / 32, DIM / 32, 3), dim3(32, 8)>>>(Wq, Wk, Wv, wf);
    wsplit_t<<<dim3(DIM / 32, DIM / 32), dim3(32, 8)>>>(Wo, woh, wol);

    gemm_qkv<<<dim3(24, SEQ / 128), 256, SMEM_G>>>(hf, wf, bq, bk, bv,
                                                   qf, kf, vf);

    flash_hf<<<dim3(SEQ / 128, NHEAD), 256, SMEM_F>>>(qf, kf, vf, aoh, aol);

    gemm_out<<<dim3(DIM / 128, SEQ / 128), 256, SMEM_G>>>(aoh, aol, woh, wol,
                                                          bo, proj);

    ln_kernel<<<SEQ, 256>>>(h, proj, gamma, beta, out);
}

// round 8
// speedup vs baseline: 8.1509x; 1.1794x over previous
#include <cuda_runtime.h>
#include <cuda_bf16.h>
#include <cuda_fp16.h>
#include <math.h>
#include <stdint.h>

#define SEQ   4096
#define DIM   1024
#define NHEAD 16
#define DHEAD 64

// ---------------- scratch (no cudaMalloc allowed) ----------------
__device__ float  g_h   [SEQ*DIM];     // x + pe (fp32, residual)
__device__ float  g_proj[SEQ*DIM];     // final projection out (fp32)
__device__ __half g_hf[SEQ*DIM];       // x + pe (fp16, qkv GEMM input)
__device__ __half g_wf[4][DIM*DIM];    // Wq/Wk/Wv/Wo fp16, TRANSPOSED [N,K]
__device__ __half g_qf[SEQ*DIM], g_kf[SEQ*DIM], g_vf[SEQ*DIM];
__device__ __half g_aof[SEQ*DIM];      // attention out (fp16)

// ---------------- helpers ----------------
__device__ __forceinline__ uint32_t saddr(const void* p) {
    return (uint32_t)__cvta_generic_to_shared(p);
}
__device__ __forceinline__ float ex2f(float x) {
    float y; asm("ex2.approx.f32 %0, %1;" : "=f"(y) : "f"(x)); return y;
}
__device__ __forceinline__ int swzi64(int row, int col) {
    return row * 64 + ((((col >> 3) ^ row) & 7) << 3);
}
__device__ __forceinline__ void ldsm4(uint32_t* r, uint32_t a) {
    asm volatile("ldmatrix.sync.aligned.m8n8.x4.shared.b16 {%0,%1,%2,%3},[%4];"
                 : "=r"(r[0]), "=r"(r[1]), "=r"(r[2]), "=r"(r[3]) : "r"(a));
}
__device__ __forceinline__ void ldsm4t(uint32_t* r, uint32_t a) {
    asm volatile("ldmatrix.sync.aligned.m8n8.x4.trans.shared.b16 {%0,%1,%2,%3},[%4];"
                 : "=r"(r[0]), "=r"(r[1]), "=r"(r[2]), "=r"(r[3]) : "r"(a));
}
__device__ __forceinline__ void mma_hf(float* c, const uint32_t* a,
                                       uint32_t b0, uint32_t b1) {
    asm volatile(
        "mma.sync.aligned.m16n8k16.row.col.f32.f16.f16.f32 "
        "{%0,%1,%2,%3},{%4,%5,%6,%7},{%8,%9},{%0,%1,%2,%3};"
        : "+f"(c[0]), "+f"(c[1]), "+f"(c[2]), "+f"(c[3])
        : "r"(a[0]), "r"(a[1]), "r"(a[2]), "r"(a[3]), "r"(b0), "r"(b1));
}
__device__ __forceinline__ uint32_t packh(float a, float b) {
    __half2 t = __floats2half2_rn(a, b);
    return *reinterpret_cast<uint32_t*>(&t);
}
__device__ __forceinline__ void cpasync16(void* dst, const void* src) {
    asm volatile("cp.async.cg.shared.global [%0], [%1], 16;"
                 :: "r"(saddr(dst)), "l"(src));
}
__device__ __forceinline__ void cp_commit() {
    asm volatile("cp.async.commit_group;" ::: "memory");
}
template <int N> __device__ __forceinline__ void cp_wait() {
    asm volatile("cp.async.wait_group %0;" :: "n"(N) : "memory");
}

// ---------------- h = x + pe (fp32 + fp16) ----------------
__global__ __launch_bounds__(256) void add_pe(const float* __restrict__ x,
                                              float* __restrict__ h,
                                              __half* __restrict__ hf) {
    int row = blockIdx.x;
    int c0  = threadIdx.x * 4;
    const float kf = -9.210340371976184f / (float)DIM;
    float4 xv = *reinterpret_cast<const float4*>(x + (size_t)row * DIM + c0);
    float v[4] = {xv.x, xv.y, xv.z, xv.w};
    float o[4];
#pragma unroll
    for (int e = 0; e < 4; e++) {
        int c = c0 + e;
        float div = expf((float)(c & ~1) * kf);
        float arg = (float)row * div;
        o[e] = v[e] + ((c & 1) ? cosf(arg) : sinf(arg));
    }
    size_t base = (size_t)row * DIM + c0;
    *reinterpret_cast<float4*>(h + base) = make_float4(o[0], o[1], o[2], o[3]);
    *reinterpret_cast<__half2*>(hf + base)     = __floats2half2_rn(o[0], o[1]);
    *reinterpret_cast<__half2*>(hf + base + 2) = __floats2half2_rn(o[2], o[3]);
}

// ---------------- fp16 weight transpose (4 weights): Wt[n,k] = W[k,n] --------
__global__ __launch_bounds__(256) void whalf_t(const float* __restrict__ W0,
                                               const float* __restrict__ W1,
                                               const float* __restrict__ W2,
                                               const float* __restrict__ W3,
                                               __half* __restrict__ outw) {
    __shared__ float t[32][33];
    const float* Ws[4] = {W0, W1, W2, W3};
    const float* W = Ws[blockIdx.z];
    __half* o = outw + (size_t)blockIdx.z * DIM * DIM;
    int k0 = blockIdx.x * 32, n0 = blockIdx.y * 32;
    int tx = threadIdx.x, ty = threadIdx.y;
#pragma unroll
    for (int j = 0; j < 4; j++)
        t[ty + 8 * j][tx] = W[(size_t)(k0 + ty + 8 * j) * DIM + n0 + tx];
    __syncthreads();
#pragma unroll
    for (int j = 0; j < 4; j++)
        o[(size_t)(n0 + ty + 8 * j) * DIM + k0 + tx] =
            __float2half_rn(t[tx][ty + 8 * j]);
}

// ---------------- fused q/k/v GEMM: single fp16 product ----------------
// grid (24, 32): blockIdx.x>>3 selects {q,k,v}; q gets scale*log2e folded in.
__global__ __launch_bounds__(256, 2) void gemm_qkv(
    const __half* __restrict__ A, const __half* __restrict__ Wf,
    const float* __restrict__ bq, const float* __restrict__ bk,
    const float* __restrict__ bv,
    __half* __restrict__ Qo, __half* __restrict__ Ko, __half* __restrict__ Vo) {
    extern __shared__ __half smq[];
    const int tid  = threadIdx.x;
    const int warp = tid >> 5, lane = tid & 31;
    const int g = lane >> 2, t4 = lane & 3;
    const int lr = lane & 7, sub = lane >> 3;
    const int wm = warp & 3, wn = warp >> 2;
    const int wsel = blockIdx.x >> 3;
    const int n0 = (blockIdx.x & 7) * 128;
    const int m0 = blockIdx.y * 128;
    const __half* B = Wf + (size_t)wsel * DIM * DIM;
    const float* bias = (wsel == 0) ? bq : ((wsel == 1) ? bk : bv);
    __half* C = (wsel == 0) ? Qo : ((wsel == 1) ? Ko : Vo);
    const float osc = (wsel == 0) ? 0.18033688011112042f : 1.0f;  // (1/8)*log2e

    auto load_chunk = [&](int kb, int st) {
        __half* sA = smq + st * 16384;
        __half* sB = sA + 8192;
#pragma unroll
        for (int i = 0; i < 4; i++) {
            int id = tid + i * 256;          // 0..1023
            int r = id >> 3, cc = id & 7;
            int sidx = (r * 8 + ((cc ^ r) & 7)) * 8;
            cpasync16(sA + sidx, A + (size_t)(m0 + r) * DIM + kb * 64 + cc * 8);
            cpasync16(sB + sidx, B + (size_t)(n0 + r) * DIM + kb * 64 + cc * 8);
        }
    };

    float acc[2][8][4];
#pragma unroll
    for (int mt = 0; mt < 2; mt++)
#pragma unroll
        for (int nt = 0; nt < 8; nt++)
#pragma unroll
            for (int e = 0; e < 4; e++) acc[mt][nt][e] = 0.f;

    load_chunk(0, 0);
    cp_commit();

    const int NCH = DIM / 64;            // 16
    for (int kb = 0; kb < NCH; kb++) {
        int st = kb & 1;
        if (kb + 1 < NCH) { load_chunk(kb + 1, st ^ 1); cp_commit(); cp_wait<1>(); }
        else              { cp_wait<0>(); }
        __syncthreads();
        __half* sA = smq + st * 16384;
        __half* sB = sA + 8192;
#pragma unroll
        for (int kk = 0; kk < 4; kk++) {
            uint32_t af[2][4];
#pragma unroll
            for (int mt = 0; mt < 2; mt++)
                ldsm4(af[mt], saddr(sA + swzi64(wm * 32 + mt * 16 + lr + (sub & 1) * 8,
                                                kk * 16 + (sub >> 1) * 8)));
#pragma unroll
            for (int ntt = 0; ntt < 4; ntt++) {
                uint32_t bfg[4];
                ldsm4(bfg, saddr(sB + swzi64(wn * 64 + ntt * 16 + lr + (sub >> 1) * 8,
                                             kk * 16 + (sub & 1) * 8)));
#pragma unroll
                for (int mt = 0; mt < 2; mt++) {
                    mma_hf(acc[mt][2 * ntt],     af[mt], bfg[0], bfg[1]);
                    mma_hf(acc[mt][2 * ntt + 1], af[mt], bfg[2], bfg[3]);
                }
            }
        }
        __syncthreads();
    }

#pragma unroll
    for (int mt = 0; mt < 2; mt++) {
#pragma unroll
        for (int nt = 0; nt < 8; nt++) {
            int row0 = m0 + wm * 32 + mt * 16 + g;
            int col  = n0 + wn * 64 + nt * 8 + t4 * 2;
            float b0 = bias[col], b1 = bias[col + 1];
            *reinterpret_cast<__half2*>(C + (size_t)row0 * DIM + col) =
                __floats2half2_rn((acc[mt][nt][0] + b0) * osc,
                                  (acc[mt][nt][1] + b1) * osc);
            *reinterpret_cast<__half2*>(C + (size_t)(row0 + 8) * DIM + col) =
                __floats2half2_rn((acc[mt][nt][2] + b0) * osc,
                                  (acc[mt][nt][3] + b1) * osc);
        }
    }
}

// ---------------- out-proj GEMM: single fp16 product, fp32 out ----------------
__global__ __launch_bounds__(256, 2) void gemm_out(
    const __half* __restrict__ A, const __half* __restrict__ B,
    const float* __restrict__ bias, float* __restrict__ Cf) {
    extern __shared__ __half smq[];
    const int tid  = threadIdx.x;
    const int warp = tid >> 5, lane = tid & 31;
    const int g = lane >> 2, t4 = lane & 3;
    const int lr = lane & 7, sub = lane >> 3;
    const int wm = warp & 3, wn = warp >> 2;
    const int m0 = blockIdx.y * 128, n0 = blockIdx.x * 128;

    auto load_chunk = [&](int kb, int st) {
        __half* sA = smq + st * 16384;
        __half* sB = sA + 8192;
#pragma unroll
        for (int i = 0; i < 4; i++) {
            int id = tid + i * 256;
            int r = id >> 3, cc = id & 7;
            int sidx = (r * 8 + ((cc ^ r) & 7)) * 8;
            cpasync16(sA + sidx, A + (size_t)(m0 + r) * DIM + kb * 64 + cc * 8);
            cpasync16(sB + sidx, B + (size_t)(n0 + r) * DIM + kb * 64 + cc * 8);
        }
    };

    float acc[2][8][4];
#pragma unroll
    for (int mt = 0; mt < 2; mt++)
#pragma unroll
        for (int nt = 0; nt < 8; nt++)
#pragma unroll
            for (int e = 0; e < 4; e++) acc[mt][nt][e] = 0.f;

    load_chunk(0, 0);
    cp_commit();

    const int NCH = DIM / 64;
    for (int kb = 0; kb < NCH; kb++) {
        int st = kb & 1;
        if (kb + 1 < NCH) { load_chunk(kb + 1, st ^ 1); cp_commit(); cp_wait<1>(); }
        else              { cp_wait<0>(); }
        __syncthreads();
        __half* sA = smq + st * 16384;
        __half* sB = sA + 8192;
#pragma unroll
        for (int kk = 0; kk < 4; kk++) {
            uint32_t af[2][4];
#pragma unroll
            for (int mt = 0; mt < 2; mt++)
                ldsm4(af[mt], saddr(sA + swzi64(wm * 32 + mt * 16 + lr + (sub & 1) * 8,
                                                kk * 16 + (sub >> 1) * 8)));
#pragma unroll
            for (int ntt = 0; ntt < 4; ntt++) {
                uint32_t bfg[4];
                ldsm4(bfg, saddr(sB + swzi64(wn * 64 + ntt * 16 + lr + (sub >> 1) * 8,
                                             kk * 16 + (sub & 1) * 8)));
#pragma unroll
                for (int mt = 0; mt < 2; mt++) {
                    mma_hf(acc[mt][2 * ntt],     af[mt], bfg[0], bfg[1]);
                    mma_hf(acc[mt][2 * ntt + 1], af[mt], bfg[2], bfg[3]);
                }
            }
        }
        __syncthreads();
    }

#pragma unroll
    for (int mt = 0; mt < 2; mt++) {
#pragma unroll
        for (int nt = 0; nt < 8; nt++) {
            int row0 = m0 + wm * 32 + mt * 16 + g;
            int col  = n0 + wn * 64 + nt * 8 + t4 * 2;
            float b0 = bias[col], b1 = bias[col + 1];
            *reinterpret_cast<float2*>(Cf + (size_t)row0 * DIM + col) =
                make_float2(acc[mt][nt][0] + b0, acc[mt][nt][1] + b1);
            *reinterpret_cast<float2*>(Cf + (size_t)(row0 + 8) * DIM + col) =
                make_float2(acc[mt][nt][2] + b0, acc[mt][nt][3] + b1);
        }
    }
}

// ---------------- flash attention: fp16, pre-scaled q, deferred l-reduce -----
__global__ __launch_bounds__(256, 2) void flash_hf(
    const __half* __restrict__ Qf,
    const __half* __restrict__ Kf,
    const __half* __restrict__ Vf,
    __half* __restrict__ Of) {
    extern __shared__ __half smh[];
    __half* sQ = smh;                    // 128 x 64

    const int tid  = threadIdx.x;
    const int warp = tid >> 5, lane = tid & 31;
    const int g = lane >> 2, t4 = lane & 3;
    const int lr = lane & 7, sub = lane >> 3;
    const int rbase = warp * 16;
    const int head  = blockIdx.y;
    const int qt    = blockIdx.x;

    {
        const __half* qb = Qf + (size_t)(qt * 128) * DIM + head * DHEAD;
#pragma unroll
        for (int i = 0; i < 4; i++) {
            int id = tid + i * 256;
            int r = id >> 3, cc = id & 7;
            cpasync16(sQ + (r * 64 + ((cc ^ r) & 7) * 8),
                      qb + (size_t)r * DIM + cc * 8);
        }
    }
    auto load_kv = [&](int t, int st) {
        __half* sK = smh + 8192  + st * 4096;
        __half* sV = smh + 16384 + st * 4096;
        const size_t base = (size_t)(t * 64) * DIM + head * DHEAD;
#pragma unroll
        for (int i = 0; i < 2; i++) {
            int id = tid + i * 256;
            int r = id >> 3, cc = id & 7;
            int sidx = (r * 8 + ((cc ^ r) & 7)) * 8;
            cpasync16(sK + sidx, Kf + base + (size_t)r * DIM + cc * 8);
            cpasync16(sV + sidx, Vf + base + (size_t)r * DIM + cc * 8);
        }
    };

    float m_i[2], l_i[2], o[8][4];
    m_i[0] = m_i[1] = -1e30f;
    l_i[0] = l_i[1] = 0.f;               // per-thread partial (4 cols each row)
#pragma unroll
    for (int nt = 0; nt < 8; nt++)
#pragma unroll
        for (int e = 0; e < 4; e++) o[nt][e] = 0.f;

    const int NT = SEQ / 64;

    load_kv(0, 0);
    cp_commit();

    for (int t = 0; t < NT; t++) {
        int st = t & 1;
        if (t + 1 < NT) { load_kv(t + 1, st ^ 1); cp_commit(); cp_wait<1>(); }
        else            { cp_wait<0>(); }
        __syncthreads();
        __half* sK = smh + 8192  + st * 4096;
        __half* sV = smh + 16384 + st * 4096;

        // ---- S = Q * K^T (q pre-scaled by (1/8)*log2e) ----
        float s[8][4];
#pragma unroll
        for (int nt = 0; nt < 8; nt++)
#pragma unroll
            for (int e = 0; e < 4; e++) s[nt][e] = 0.f;
#pragma unroll
        for (int kk = 0; kk < 4; kk++) {
            uint32_t qf[4];
            ldsm4(qf, saddr(sQ + swzi64(rbase + lr + (sub & 1) * 8,
                                        kk * 16 + (sub >> 1) * 8)));
#pragma unroll
            for (int ntt = 0; ntt < 4; ntt++) {
                uint32_t kf[4];
                ldsm4(kf, saddr(sK + swzi64(ntt * 16 + lr + (sub >> 1) * 8,
                                            kk * 16 + (sub & 1) * 8)));
                mma_hf(s[2 * ntt],     qf, kf[0], kf[1]);
                mma_hf(s[2 * ntt + 1], qf, kf[2], kf[3]);
            }
        }

        // ---- online softmax (log2 domain; l kept per-thread) ----
#pragma unroll
        for (int r = 0; r < 2; r++) {
            float mx = -1e30f;
#pragma unroll
            for (int j = 0; j < 8; j++)
                mx = fmaxf(mx, fmaxf(s[j][2 * r], s[j][2 * r + 1]));
            mx = fmaxf(mx, __shfl_xor_sync(0xffffffffu, mx, 1));
            mx = fmaxf(mx, __shfl_xor_sync(0xffffffffu, mx, 2));
            float mnew = fmaxf(m_i[r], mx);
            float corr = ex2f(m_i[r] - mnew);
            m_i[r] = mnew;
            float rs = 0.f;
#pragma unroll
            for (int j = 0; j < 8; j++) {
                float p0 = ex2f(s[j][2 * r] - mnew);
                float p1 = ex2f(s[j][2 * r + 1] - mnew);
                s[j][2 * r] = p0; s[j][2 * r + 1] = p1;
                rs += p0 + p1;
            }
            l_i[r] = l_i[r] * corr + rs;
#pragma unroll
            for (int nt = 0; nt < 8; nt++) {
                o[nt][2 * r]     *= corr;
                o[nt][2 * r + 1] *= corr;
            }
        }

        // ---- O += P * V ----
#pragma unroll
        for (int kk = 0; kk < 4; kk++) {
            int j0 = 2 * kk, j1 = j0 + 1;
            uint32_t aH[4];
            aH[0] = packh(s[j0][0], s[j0][1]);
            aH[1] = packh(s[j0][2], s[j0][3]);
            aH[2] = packh(s[j1][0], s[j1][1]);
            aH[3] = packh(s[j1][2], s[j1][3]);
#pragma unroll
            for (int ntt = 0; ntt < 4; ntt++) {
                uint32_t vf[4];
                ldsm4t(vf, saddr(sV + swzi64(kk * 16 + lr + (sub & 1) * 8,
                                             ntt * 16 + (sub >> 1) * 8)));
                mma_hf(o[2 * ntt],     aH, vf[0], vf[1]);
                mma_hf(o[2 * ntt + 1], aH, vf[2], vf[3]);
            }
        }
        __syncthreads();
    }

    // final l reduction across the 4 lanes sharing each row
#pragma unroll
    for (int r = 0; r < 2; r++) {
        l_i[r] += __shfl_xor_sync(0xffffffffu, l_i[r], 1);
        l_i[r] += __shfl_xor_sync(0xffffffffu, l_i[r], 2);
    }
    float inv0 = 1.f / l_i[0], inv1 = 1.f / l_i[1];
#pragma unroll
    for (int nt = 0; nt < 8; nt++) {
        int row0 = qt * 128 + rbase + g;
        int col  = head * DHEAD + nt * 8 + t4 * 2;
        *reinterpret_cast<__half2*>(Of + (size_t)row0 * DIM + col) =
            __floats2half2_rn(o[nt][0] * inv0, o[nt][1] * inv0);
        *reinterpret_cast<__half2*>(Of + (size_t)(row0 + 8) * DIM + col) =
            __floats2half2_rn(o[nt][2] * inv1, o[nt][3] * inv1);
    }
}

// ---------------- residual + layernorm ----------------
__global__ __launch_bounds__(256) void ln_kernel(const float* __restrict__ h,
                                                 const float* __restrict__ pr,
                                                 const float* __restrict__ gamma,
                                                 const float* __restrict__ beta,
                                                 float* __restrict__ out) {
    __shared__ float red[16];
    __shared__ float s_mu, s_rstd;
    int row = blockIdx.x, tid = threadIdx.x;
    int c0 = tid * 4;
    float4 hv = *reinterpret_cast<const float4*>(h  + (size_t)row * DIM + c0);
    float4 pv = *reinterpret_cast<const float4*>(pr + (size_t)row * DIM + c0);
    float y[4] = {hv.x + pv.x, hv.y + pv.y, hv.z + pv.z, hv.w + pv.w};
    float sum = y[0] + y[1] + y[2] + y[3];
    float sq  = y[0]*y[0] + y[1]*y[1] + y[2]*y[2] + y[3]*y[3];
#pragma unroll
    for (int off = 16; off; off >>= 1) {
        sum += __shfl_xor_sync(0xffffffffu, sum, off);
        sq  += __shfl_xor_sync(0xffffffffu, sq,  off);
    }
    int w = tid >> 5;
    if ((tid & 31) == 0) { red[w] = sum; red[8 + w] = sq; }
    __syncthreads();
    if (tid == 0) {
        float ts = 0.f, tq = 0.f;
        for (int i = 0; i < 8; i++) { ts += red[i]; tq += red[8 + i]; }
        float mu = ts / (float)DIM;
        s_mu   = mu;
        s_rstd = rsqrtf(tq / (float)DIM - mu * mu + 1e-5f);
    }
    __syncthreads();
    float4 gv = *reinterpret_cast<const float4*>(gamma + c0);
    float4 bv = *reinterpret_cast<const float4*>(beta  + c0);
    float mu = s_mu, rs = s_rstd;
    float4 ov;
    ov.x = (y[0] - mu) * rs * gv.x + bv.x;
    ov.y = (y[1] - mu) * rs * gv.y + bv.y;
    ov.z = (y[2] - mu) * rs * gv.z + bv.z;
    ov.w = (y[3] - mu) * rs * gv.w + bv.w;
    *reinterpret_cast<float4*>(out + (size_t)row * DIM + c0) = ov;
}

// ---------------------------------------------------------------------------
extern "C" void kernel_launch(void* const* d_in, const int* in_sizes, int n_in,
                              void* d_out, int out_size) {
    (void)in_sizes; (void)n_in; (void)out_size;
    const float* x     = (const float*)d_in[0];
    const float* Wq    = (const float*)d_in[1];
    const float* bq    = (const float*)d_in[2];
    const float* Wk    = (const float*)d_in[3];
    const float* bk    = (const float*)d_in[4];
    const float* Wv    = (const float*)d_in[5];
    const float* bv    = (const float*)d_in[6];
    const float* Wo    = (const float*)d_in[7];
    const float* bo    = (const float*)d_in[8];
    const float* gamma = (const float*)d_in[9];
    const float* beta  = (const float*)d_in[10];
    float* out = (float*)d_out;

    void* p;
    cudaGetSymbolAddress(&p, g_h);    float* h    = (float*)p;
    cudaGetSymbolAddress(&p, g_proj); float* proj = (float*)p;
    cudaGetSymbolAddress(&p, g_hf);   __half* hf = (__half*)p;
    cudaGetSymbolAddress(&p, g_wf);   __half* wf = (__half*)p;
    cudaGetSymbolAddress(&p, g_qf);   __half* qf = (__half*)p;
    cudaGetSymbolAddress(&p, g_kf);   __half* kf = (__half*)p;
    cudaGetSymbolAddress(&p, g_vf);   __half* vf = (__half*)p;
    cudaGetSymbolAddress(&p, g_aof);  __half* aof = (__half*)p;

    const int SMEM_G = 65536;            // 2 stages x 32KB
    const int SMEM_F = 49152;
    cudaFuncSetAttribute(gemm_qkv,
                         cudaFuncAttributeMaxDynamicSharedMemorySize, SMEM_G);
    cudaFuncSetAttribute(gemm_out,
                         cudaFuncAttributeMaxDynamicSharedMemorySize, SMEM_G);
    cudaFuncSetAttribute(flash_hf,
                         cudaFuncAttributeMaxDynamicSharedMemorySize, SMEM_F);

    add_pe<<<SEQ, 256>>>(x, h, hf);
    whalf_t<<<dim3(DIM / 32, DIM / 32, 4), dim3(32, 8)>>>(Wq, Wk, Wv, Wo, wf);

    gemm_qkv<<<dim3(24, SEQ / 128), 256, SMEM_G>>>(hf, wf, bq, bk, bv,
                                                   qf, kf, vf);

    flash_hf<<<dim3(SEQ / 128, NHEAD), 256, SMEM_F>>>(qf, kf, vf, aof);

    gemm_out<<<dim3(DIM / 128, SEQ / 128), 256, SMEM_G>>>(
        aof, wf + 3 * (size_t)DIM * DIM, bo, proj);

    ln_kernel<<<SEQ, 256>>>(h, proj, gamma, beta, out);
}